// round 14
// baseline (speedup 1.0000x reference)
#include <cuda_runtime.h>
#include <cuda_bf16.h>
#include <cuda_fp16.h>
#include <math.h>
#include <stdint.h>

#define D 128
#define NMAX 100000
#define EMAX 800000
#define RELN 2000
#define CHUNK 512
#define NB_MAX 256

// ---------------- static device scratch (no runtime allocation) ----------------
__device__ __align__(16) __half g_Xh1[NMAX * D];
__device__ __align__(16) __half g_Xh2[NMAX * D];
__device__ __align__(16) float g_HA[NMAX * D];
__device__ __align__(16) float g_HB[NMAX * D];
__device__ __align__(16) float g_relA[RELN * D];
__device__ __align__(16) float g_relB[RELN * D];
__device__ __align__(16) __half g_G1[RELN * D];
__device__ __align__(16) __half g_G2[RELN * D];
__device__ __align__(16) __half g_G1b[RELN * D];
__device__ __align__(16) __half g_G2b[RELN * D];
__device__ __align__(16) unsigned g_W1hi[D * 64];
__device__ __align__(16) unsigned g_W1lo[D * 64];
__device__ __align__(16) unsigned g_W2hi[D * 64];
__device__ __align__(16) unsigned g_W2lo[D * 64];
__device__ __align__(16) float g_bp1[D];
__device__ __align__(16) float g_bp2[D];
__device__ __align__(16) float g_stats[6 * D];
__device__ __align__(16) float g_ksc[NMAX];
__device__ __align__(16) float g_lesc[NMAX];
// CSR scratch (separate per graph so builds are stream-parallel)
__device__ int g_cnt1[NMAX], g_cnt2[NMAX];
__device__ int g_cur1[NMAX], g_cur2[NMAX];
__device__ int g_off1[NMAX + 1];
__device__ int g_off2[NMAX + 1];
__device__ int g_bs1[NB_MAX], g_bs2[NB_MAX];
__device__ __align__(8) int2 g_eSA1[EMAX];
__device__ __align__(8) int2 g_eSA2[EMAX];

// ================= CSR build =================
__global__ void k_hist(const int* __restrict__ dst, int* __restrict__ cnt, int E) {
    int e = blockIdx.x * blockDim.x + threadIdx.x;
    if (e < E) atomicAdd(&cnt[dst[e]], 1);
}

__global__ void k_scan_sum(const int* __restrict__ cnt, int* __restrict__ bs, int n) {
    __shared__ int sh[CHUNK];
    int t = threadIdx.x;
    int i = blockIdx.x * CHUNK + t;
    sh[t] = (i < n) ? cnt[i] : 0;
    __syncthreads();
#pragma unroll
    for (int o = CHUNK / 2; o; o >>= 1) {
        if (t < o) sh[t] += sh[t + o];
        __syncthreads();
    }
    if (t == 0) bs[blockIdx.x] = sh[0];
}

__global__ void k_scan_top(int* __restrict__ bs, int nb) {
    __shared__ int sh[256];
    int t = threadIdx.x;
    int v = (t < nb) ? bs[t] : 0;
    sh[t] = v;
    __syncthreads();
#pragma unroll
    for (int o = 1; o < 256; o <<= 1) {
        int x = (t >= o) ? sh[t - o] : 0;
        __syncthreads();
        sh[t] += x;
        __syncthreads();
    }
    if (t < nb) bs[t] = sh[t] - v;
}

__global__ void k_scan_out(const int* __restrict__ cnt, const int* __restrict__ bs,
                           int* __restrict__ off, int* __restrict__ cur, int n, int E) {
    __shared__ int sh[CHUNK];
    int t = threadIdx.x;
    int i = blockIdx.x * CHUNK + t;
    int v = (i < n) ? cnt[i] : 0;
    sh[t] = v;
    __syncthreads();
#pragma unroll
    for (int o = 1; o < CHUNK; o <<= 1) {
        int x = (t >= o) ? sh[t - o] : 0;
        __syncthreads();
        sh[t] += x;
        __syncthreads();
    }
    if (i < n) {
        int e = bs[blockIdx.x] + sh[t] - v;
        off[i] = e;
        cur[i] = e;
    }
    if (i == 0) off[n] = E;
}

__global__ void k_fill(const int* __restrict__ src, const int* __restrict__ dst,
                       const int* __restrict__ attr, int* __restrict__ cur,
                       int2* __restrict__ eSA, int E) {
    int e = blockIdx.x * blockDim.x + threadIdx.x;
    if (e >= E) return;
    int p = atomicAdd(&cur[dst[e]], 1);
    eSA[p] = make_int2(src[e], attr[e]);
}

// per-node output scales from histogram counts
__global__ void k_scales(const int* __restrict__ cnt1, const int* __restrict__ cnt2,
                         float* __restrict__ ksc, float* __restrict__ lesc, int n) {
    int v = blockIdx.x * blockDim.x + threadIdx.x;
    if (v >= n) return;
    int d1 = cnt1[v] > 0;
    int d2 = cnt2[v] > 0;
    ksc[v] = rsqrtf((float)(1 + 2 * d1 + 2 * d2));
    int k2 = d1 + d2;
    lesc[v] = k2 ? rsqrtf((float)k2) : 0.f;
}

// ---------------- small GEMM: C[M,128] = A @ W + b ----------------
__global__ void k_small_gemm(const float* __restrict__ A, const float* __restrict__ W,
                             const float* __restrict__ b, float* __restrict__ C, int M) {
    __shared__ float As[8][D];
    int r0 = blockIdx.x * 8;
    int c = threadIdx.x;
#pragma unroll
    for (int r = 0; r < 8; r++) {
        int rr = r0 + r;
        As[r][c] = (rr < M) ? A[(size_t)rr * D + c] : 0.f;
    }
    __syncthreads();
    float acc[8];
    float bias = b[c];
#pragma unroll
    for (int r = 0; r < 8; r++) acc[r] = bias;
    for (int k = 0; k < D; k++) {
        float w = W[k * D + c];
#pragma unroll
        for (int r = 0; r < 8; r++) acc[r] = fmaf(As[r][k], w, acc[r]);
    }
#pragma unroll
    for (int r = 0; r < 8; r++) {
        int rr = r0 + r;
        if (rr < M) C[(size_t)rr * D + c] = acc[r];
    }
}

// dual gate GEMM (fp16 output)
__global__ void k_gate_gemm2(const float* __restrict__ A,
                             const float* __restrict__ W1, const float* __restrict__ b1,
                             __half* __restrict__ C1,
                             const float* __restrict__ W2, const float* __restrict__ b2,
                             __half* __restrict__ C2, int M) {
    __shared__ float As[8][D];
    int r0 = blockIdx.x * 8;
    int c = threadIdx.x;
#pragma unroll
    for (int r = 0; r < 8; r++) {
        int rr = r0 + r;
        As[r][c] = (rr < M) ? A[(size_t)rr * D + c] : 0.f;
    }
    __syncthreads();
    float a1[8], a2[8];
    float bb1 = b1[c], bb2 = b2[c];
#pragma unroll
    for (int r = 0; r < 8; r++) { a1[r] = bb1; a2[r] = bb2; }
    for (int k = 0; k < D; k++) {
        float w1 = W1[k * D + c];
        float w2 = W2[k * D + c];
#pragma unroll
        for (int r = 0; r < 8; r++) {
            float av = As[r][k];
            a1[r] = fmaf(av, w1, a1[r]);
            a2[r] = fmaf(av, w2, a2[r]);
        }
    }
#pragma unroll
    for (int r = 0; r < 8; r++) {
        int rr = r0 + r;
        if (rr < M) {
            C1[(size_t)rr * D + c] = __float2half_rn(1.f / (1.f + expf(-a1[r])));
            C2[(size_t)rr * D + c] = __float2half_rn(1.f / (1.f + expf(-a2[r])));
        }
    }
}

// -------- fold BatchNorm into GEMM weights; emit W^T as bf16 hi/lo + bias --------
__global__ void k_prep_wb(const float* __restrict__ sum, const float* __restrict__ sq,
                          const float* __restrict__ gamma, const float* __restrict__ beta,
                          const float* __restrict__ W, const float* __restrict__ b,
                          unsigned* __restrict__ Whi, unsigned* __restrict__ Wlo,
                          float* __restrict__ bp, float invN) {
    __shared__ float sa[D], sc[D];
    int j = threadIdx.x;
    float m = sum[j] * invN;
    float v = sq[j] * invN - m * m;
    float a = rsqrtf(v + 1e-5f) * gamma[j];
    sa[j] = a;
    sc[j] = beta[j] - m * a;
    __syncthreads();
    float acc = b[j];
    for (int k = 0; k < D; k += 2) {
        float w0r = W[k * D + j];
        float w1r = W[(k + 1) * D + j];
        acc = fmaf(sc[k], w0r, acc);
        acc = fmaf(sc[k + 1], w1r, acc);
        float w0 = sa[k] * w0r;
        float w1 = sa[k + 1] * w1r;
        __nv_bfloat16 h0 = __float2bfloat16_rn(w0);
        __nv_bfloat16 h1 = __float2bfloat16_rn(w1);
        float r0 = w0 - __bfloat162float(h0);
        float r1 = w1 - __bfloat162float(h1);
        __nv_bfloat16 l0 = __float2bfloat16_rn(r0);
        __nv_bfloat16 l1 = __float2bfloat16_rn(r1);
        Whi[j * 64 + k / 2] = (unsigned)__bfloat16_as_ushort(h0) |
                              ((unsigned)__bfloat16_as_ushort(h1) << 16);
        Wlo[j * 64 + k / 2] = (unsigned)__bfloat16_as_ushort(l0) |
                              ((unsigned)__bfloat16_as_ushort(l1) << 16);
    }
    bp[j] = acc;
}

// ================ tensor-core GEMM via mma.sync (bf16 2-way split) ================
#define PADW 68
#define ROWB (PADW * 4)
#define T_BYTES (128 * ROWB)

__device__ __forceinline__ void split8(const float* x, uint4& hv, uint4& lv) {
    unsigned h[4], l[4];
#pragma unroll
    for (int i = 0; i < 4; i++) {
        float a = x[2 * i], b = x[2 * i + 1];
        __nv_bfloat16 ha = __float2bfloat16_rn(a);
        __nv_bfloat16 hb = __float2bfloat16_rn(b);
        float ra = a - __bfloat162float(ha);
        float rb = b - __bfloat162float(hb);
        __nv_bfloat16 la = __float2bfloat16_rn(ra);
        __nv_bfloat16 lb = __float2bfloat16_rn(rb);
        h[i] = (unsigned)__bfloat16_as_ushort(ha) | ((unsigned)__bfloat16_as_ushort(hb) << 16);
        l[i] = (unsigned)__bfloat16_as_ushort(la) | ((unsigned)__bfloat16_as_ushort(lb) << 16);
    }
    hv = make_uint4(h[0], h[1], h[2], h[3]);
    lv = make_uint4(l[0], l[1], l[2], l[3]);
}

__device__ __forceinline__ void mma16816(float* c, const uint32_t* a,
                                         uint32_t b0, uint32_t b1) {
    asm volatile(
        "mma.sync.aligned.m16n8k16.row.col.f32.bf16.bf16.f32 "
        "{%0,%1,%2,%3}, {%4,%5,%6,%7}, {%8,%9}, {%0,%1,%2,%3};"
        : "+f"(c[0]), "+f"(c[1]), "+f"(c[2]), "+f"(c[3])
        : "r"(a[0]), "r"(a[1]), "r"(a[2]), "r"(a[3]), "r"(b0), "r"(b1));
}

__device__ __forceinline__ void gemm_core(const char* sm, int offA_hi, int offA_lo,
                                          int offW_hi, int offW_lo,
                                          const float* sBias, __half* C,
                                          int rowBase, int M, int tid) {
    const int lane = tid & 31, wid = tid >> 5;
    const int gid = lane >> 2, tig = lane & 3;
    const int wr = wid & 3;
    const int wc = wid >> 2;

    float acc[2][8][4];
#pragma unroll
    for (int m = 0; m < 2; m++)
#pragma unroll
        for (int nt = 0; nt < 8; nt++)
#pragma unroll
            for (int j = 0; j < 4; j++) acc[m][nt][j] = 0.f;

    const uint32_t* Ahi = (const uint32_t*)(sm + offA_hi);
    const uint32_t* Alo = (const uint32_t*)(sm + offA_lo);
    const uint32_t* Whi = (const uint32_t*)(sm + offW_hi);
    const uint32_t* Wlo = (const uint32_t*)(sm + offW_lo);

#pragma unroll
    for (int p = 0; p < 3; p++) {
        const uint32_t* Aw = (p == 2) ? Alo : Ahi;
        const uint32_t* Bw = (p == 1) ? Wlo : Whi;
#pragma unroll
        for (int kc = 0; kc < 8; kc++) {
            int kw = kc * 8 + tig;
            uint32_t a[2][4];
#pragma unroll
            for (int m = 0; m < 2; m++) {
                int rb = wr * 32 + m * 16 + gid;
                a[m][0] = Aw[rb * PADW + kw];
                a[m][1] = Aw[(rb + 8) * PADW + kw];
                a[m][2] = Aw[rb * PADW + kw + 4];
                a[m][3] = Aw[(rb + 8) * PADW + kw + 4];
            }
#pragma unroll
            for (int nt = 0; nt < 8; nt++) {
                int nr = wc * 64 + nt * 8 + gid;
                uint32_t b0 = Bw[nr * PADW + kw];
                uint32_t b1 = Bw[nr * PADW + kw + 4];
                mma16816(acc[0][nt], a[0], b0, b1);
                mma16816(acc[1][nt], a[1], b0, b1);
            }
        }
    }
#pragma unroll
    for (int m = 0; m < 2; m++) {
        int row0 = rowBase + wr * 32 + m * 16 + gid;
#pragma unroll
        for (int nt = 0; nt < 8; nt++) {
            int col = wc * 64 + nt * 8 + 2 * tig;
            float bb0 = sBias[col], bb1 = sBias[col + 1];
            if (row0 < M) {
                __half2 o = make_half2(__float2half_rn(acc[m][nt][0] + bb0),
                                       __float2half_rn(acc[m][nt][1] + bb1));
                ((__half2*)C)[(size_t)row0 * 64 + (col >> 1)] = o;
            }
            if (row0 + 8 < M) {
                __half2 o = make_half2(__float2half_rn(acc[m][nt][2] + bb0),
                                       __float2half_rn(acc[m][nt][3] + bb1));
                ((__half2*)C)[(size_t)(row0 + 8) * 64 + (col >> 1)] = o;
            }
        }
    }
}

// ---- single-output GEMM (layer 1) ----
#define S_BIAS 0
#define S_AHI  512
#define S_ALO  (S_AHI + T_BYTES)
#define S_WHI  (S_ALO + T_BYTES)
#define S_WLO  (S_WHI + T_BYTES)
#define SMEM_MMA  (S_WLO + T_BYTES)            // 139776

__global__ __launch_bounds__(256, 1)
void k_gemm_mma(const float* __restrict__ A, const uint4* __restrict__ WhiG,
                const uint4* __restrict__ WloG, const float* __restrict__ bp,
                __half* __restrict__ C, int M) {
    extern __shared__ char sm2[];
    const int tid = threadIdx.x;
    const int rowBase = blockIdx.x * 128;
    if (tid < 128) ((float*)(sm2 + S_BIAS))[tid] = bp[tid];
#pragma unroll
    for (int i = 0; i < 8; i++) {
        int idx = tid + i * 256;
        int r = idx >> 4, q = idx & 15;
        ((uint4*)(sm2 + S_WHI))[r * 17 + q] = WhiG[idx];
        ((uint4*)(sm2 + S_WLO))[r * 17 + q] = WloG[idx];
    }
#pragma unroll
    for (int i = 0; i < 8; i++) {
        int idx = tid + i * 256;
        int r = idx >> 4, q = idx & 15;
        int grow = rowBase + r;
        float x[8] = {0.f, 0.f, 0.f, 0.f, 0.f, 0.f, 0.f, 0.f};
        if (grow < M) {
            float4 v0 = ((const float4*)A)[(size_t)grow * 32 + q * 2];
            float4 v1 = ((const float4*)A)[(size_t)grow * 32 + q * 2 + 1];
            x[0] = v0.x; x[1] = v0.y; x[2] = v0.z; x[3] = v0.w;
            x[4] = v1.x; x[5] = v1.y; x[6] = v1.z; x[7] = v1.w;
        }
        uint4 hv, lv;
        split8(x, hv, lv);
        ((uint4*)(sm2 + S_AHI))[r * 17 + q] = hv;
        ((uint4*)(sm2 + S_ALO))[r * 17 + q] = lv;
    }
    __syncthreads();
    gemm_core(sm2, S_AHI, S_ALO, S_WHI, S_WLO, (const float*)(sm2 + S_BIAS),
              C, rowBase, M, tid);
}

// ---- dual-output GEMM (layer 0: same A, two weight sets) ----
#define D_BIAS 0
#define D_AHI  1024
#define D_ALO  (D_AHI + T_BYTES)
#define D_W1HI (D_ALO + T_BYTES)
#define D_W1LO (D_W1HI + T_BYTES)
#define D_W2HI (D_W1LO + T_BYTES)
#define D_W2LO (D_W2HI + T_BYTES)
#define SMEM_MMA2 (D_W2LO + T_BYTES)           // 209920

__global__ __launch_bounds__(256, 1)
void k_gemm_mma2(const float* __restrict__ A,
                 const uint4* __restrict__ W1hiG, const uint4* __restrict__ W1loG,
                 const float* __restrict__ bp1, __half* __restrict__ C1,
                 const uint4* __restrict__ W2hiG, const uint4* __restrict__ W2loG,
                 const float* __restrict__ bp2, __half* __restrict__ C2, int M) {
    extern __shared__ char sm3[];
    const int tid = threadIdx.x;
    const int rowBase = blockIdx.x * 128;
    if (tid < 128) {
        ((float*)(sm3 + D_BIAS))[tid] = bp1[tid];
        ((float*)(sm3 + D_BIAS + 512))[tid] = bp2[tid];
    }
#pragma unroll
    for (int i = 0; i < 8; i++) {
        int idx = tid + i * 256;
        int r = idx >> 4, q = idx & 15;
        ((uint4*)(sm3 + D_W1HI))[r * 17 + q] = W1hiG[idx];
        ((uint4*)(sm3 + D_W1LO))[r * 17 + q] = W1loG[idx];
        ((uint4*)(sm3 + D_W2HI))[r * 17 + q] = W2hiG[idx];
        ((uint4*)(sm3 + D_W2LO))[r * 17 + q] = W2loG[idx];
    }
#pragma unroll
    for (int i = 0; i < 8; i++) {
        int idx = tid + i * 256;
        int r = idx >> 4, q = idx & 15;
        int grow = rowBase + r;
        float x[8] = {0.f, 0.f, 0.f, 0.f, 0.f, 0.f, 0.f, 0.f};
        if (grow < M) {
            float4 v0 = ((const float4*)A)[(size_t)grow * 32 + q * 2];
            float4 v1 = ((const float4*)A)[(size_t)grow * 32 + q * 2 + 1];
            x[0] = v0.x; x[1] = v0.y; x[2] = v0.z; x[3] = v0.w;
            x[4] = v1.x; x[5] = v1.y; x[6] = v1.z; x[7] = v1.w;
        }
        uint4 hv, lv;
        split8(x, hv, lv);
        ((uint4*)(sm3 + D_AHI))[r * 17 + q] = hv;
        ((uint4*)(sm3 + D_ALO))[r * 17 + q] = lv;
    }
    __syncthreads();
    gemm_core(sm3, D_AHI, D_ALO, D_W1HI, D_W1LO, (const float*)(sm3 + D_BIAS),
              C1, rowBase, M, tid);
    gemm_core(sm3, D_AHI, D_ALO, D_W2HI, D_W2LO, (const float*)(sm3 + D_BIAS + 512),
              C2, rowBase, M, tid);
}

// -------- column stats only (no write) --------
__global__ void k_stats(const float* __restrict__ src,
                        float* __restrict__ sum, float* __restrict__ sq, int n) {
    __shared__ float ssum[D], ssq[D];
    int tid = threadIdx.x;
    if (tid < D) { ssum[tid] = 0.f; ssq[tid] = 0.f; }
    __syncthreads();
    int lane = tid & 31;
    int warp = (blockIdx.x * blockDim.x + tid) >> 5;
    int nwarps = (gridDim.x * blockDim.x) >> 5;
    float4 ls = make_float4(0.f, 0.f, 0.f, 0.f);
    float4 lq = make_float4(0.f, 0.f, 0.f, 0.f);
    for (int row = warp; row < n; row += nwarps) {
        float4 v = ((const float4*)src)[(size_t)row * 32 + lane];
        ls.x += v.x; ls.y += v.y; ls.z += v.z; ls.w += v.w;
        lq.x += v.x * v.x; lq.y += v.y * v.y; lq.z += v.z * v.z; lq.w += v.w * v.w;
    }
    atomicAdd(&ssum[lane * 4 + 0], ls.x); atomicAdd(&ssum[lane * 4 + 1], ls.y);
    atomicAdd(&ssum[lane * 4 + 2], ls.z); atomicAdd(&ssum[lane * 4 + 3], ls.w);
    atomicAdd(&ssq [lane * 4 + 0], lq.x); atomicAdd(&ssq [lane * 4 + 1], lq.y);
    atomicAdd(&ssq [lane * 4 + 2], lq.z); atomicAdd(&ssq [lane * 4 + 3], lq.w);
    __syncthreads();
    if (tid < D) { atomicAdd(&sum[tid], ssum[tid]); atomicAdd(&sq[tid], ssq[tid]); }
}

// -------- row-normalize: dst = scale[row] * src/||src||  (scale nullptr -> 1) ----
__global__ void k_rownorm(const float* __restrict__ src, int M, float* __restrict__ dst,
                          int ldDst, float* __restrict__ dst2, int ldDst2,
                          const float* __restrict__ scale) {
    int w = (blockIdx.x * blockDim.x + threadIdx.x) >> 5;
    int lane = threadIdx.x & 31;
    if (w >= M) return;
    float4 v = ((const float4*)src)[(size_t)w * 32 + lane];
    float s = v.x * v.x + v.y * v.y + v.z * v.z + v.w * v.w;
#pragma unroll
    for (int o = 16; o; o >>= 1) s += __shfl_xor_sync(0xffffffffu, s, o);
    float sc = scale ? scale[w] : 1.f;
    float inv = sc / fmaxf(sqrtf(s), 1e-12f);
    float4 o4 = make_float4(v.x * inv, v.y * inv, v.z * inv, v.w * inv);
    ((float4*)(dst + (size_t)w * ldDst))[lane] = o4;
    if (dst2) ((float4*)(dst2 + (size_t)w * ldDst2))[lane] = o4;
}

// -------- CSR gather conv v3: half-warp per edge, contiguous node ranges,
//          8 LDG.128 in flight per warp (8-edge unrolled main step) --------
__device__ __forceinline__ void fma8(float* acc, uint4 g, uint4 x) {
    __half2* gh = (__half2*)&g;
    __half2* xh = (__half2*)&x;
#pragma unroll
    for (int i = 0; i < 4; i++) {
        float2 gf = __half22float2(gh[i]);
        float2 xf = __half22float2(xh[i]);
        acc[2 * i]     = fmaf(gf.x, xf.x, acc[2 * i]);
        acc[2 * i + 1] = fmaf(gf.y, xf.y, acc[2 * i + 1]);
    }
}

__global__ void k_gather(const __half* __restrict__ X, const __half* __restrict__ G,
                         const int* __restrict__ off, const int2* __restrict__ eSA,
                         float* __restrict__ rawH,
                         float* __restrict__ normDst, int ldNorm,
                         const float* __restrict__ ksc,
                         float* __restrict__ le, const float* __restrict__ lesc,
                         float* __restrict__ sum, float* __restrict__ sq, int n) {
    __shared__ float ssum[D], ssq[D];
    int tid = threadIdx.x;
    const bool doStats = (sum != nullptr);
    if (doStats) {
        if (tid < D) { ssum[tid] = 0.f; ssq[tid] = 0.f; }
        __syncthreads();
    }
    int lane = tid & 31;
    int sub = lane & 15, half = lane >> 4;
    int warp = (blockIdx.x * blockDim.x + tid) >> 5;
    int nwarps = (gridDim.x * blockDim.x) >> 5;
    const uint4* G4 = (const uint4*)G;
    const uint4* X4 = (const uint4*)X;
    float ls0 = 0.f, ls1 = 0.f, ls2 = 0.f, ls3 = 0.f;
    float lq0 = 0.f, lq1 = 0.f, lq2 = 0.f, lq3 = 0.f;

    // contiguous node range per warp
    int per = (n + nwarps - 1) / nwarps;
    int v0 = warp * per;
    int v1 = min(n, v0 + per);
    int nb = (v0 < v1) ? off[v0] : 0;

    for (int v = v0; v < v1; v++) {
        int b0 = nb;
        int b1 = off[v + 1];
        nb = b1;
        float acc[8] = {0.f, 0.f, 0.f, 0.f, 0.f, 0.f, 0.f, 0.f};
        for (int base = b0; base < b1; base += 32) {
            int cnt = min(32, b1 - base);
            int2 sa = make_int2(0, 0);
            if (lane < cnt) sa = eSA[base + lane];
            int j = 0;
            // 8-edge step: 4 edges per half, 8 LDG.128 in flight
            for (; j + 8 <= cnt; j += 8) {
                int s[4], a[4];
#pragma unroll
                for (int u = 0; u < 4; u++) {
                    int e = j + 2 * u + half;
                    s[u] = __shfl_sync(0xffffffffu, sa.x, e);
                    a[u] = __shfl_sync(0xffffffffu, sa.y, e);
                }
                uint4 g[4], x[4];
#pragma unroll
                for (int u = 0; u < 4; u++) {
                    g[u] = G4[a[u] * 16 + sub];
                    x[u] = X4[(size_t)s[u] * 16 + sub];
                }
#pragma unroll
                for (int u = 0; u < 4; u++) fma8(acc, g[u], x[u]);
            }
            // 4-edge step
            for (; j + 4 <= cnt; j += 4) {
                int e0 = j + half, e1 = j + 2 + half;
                int s0 = __shfl_sync(0xffffffffu, sa.x, e0);
                int a0 = __shfl_sync(0xffffffffu, sa.y, e0);
                int s1 = __shfl_sync(0xffffffffu, sa.x, e1);
                int a1 = __shfl_sync(0xffffffffu, sa.y, e1);
                uint4 g0 = G4[a0 * 16 + sub];
                uint4 x0 = X4[(size_t)s0 * 16 + sub];
                uint4 g1 = G4[a1 * 16 + sub];
                uint4 x1 = X4[(size_t)s1 * 16 + sub];
                fma8(acc, g0, x0);
                fma8(acc, g1, x1);
            }
            // remainder (2 edges per step, predicated)
            for (; j < cnt; j += 2) {
                int e = min(j + half, cnt - 1);
                int s0 = __shfl_sync(0xffffffffu, sa.x, e);
                int a0 = __shfl_sync(0xffffffffu, sa.y, e);
                if (j + half < cnt) {
                    uint4 g = G4[a0 * 16 + sub];
                    uint4 x = X4[(size_t)s0 * 16 + sub];
                    fma8(acc, g, x);
                }
            }
        }
        // merge the two edge-halves (duplicate full row in both halves)
#pragma unroll
        for (int k = 0; k < 8; k++)
            acc[k] += __shfl_xor_sync(0xffffffffu, acc[k], 16);
        // row norm: reduce within the 16-lane half (covers all 128 cols)
        float ns = 0.f;
#pragma unroll
        for (int k = 0; k < 8; k++) ns += acc[k] * acc[k];
#pragma unroll
        for (int o = 1; o <= 8; o <<= 1) ns += __shfl_xor_sync(0xffffffffu, ns, o);
        float invB = 1.f / fmaxf(sqrtf(ns), 1e-12f);
        // this lane writes one float4: cols sub*8 + half*4 + [0,4)
        float4 w = make_float4(acc[half * 4 + 0], acc[half * 4 + 1],
                               acc[half * 4 + 2], acc[half * 4 + 3]);
        int q = sub * 2 + half;
        if (rawH) ((float4*)rawH)[(size_t)v * 32 + q] = w;
        float s1v = invB * ksc[v];
        ((float4*)(normDst + (size_t)v * ldNorm))[q] =
            make_float4(w.x * s1v, w.y * s1v, w.z * s1v, w.w * s1v);
        if (le) {
            float s2 = invB * lesc[v];
            ((float4*)(le + (size_t)v * 256))[q] =
                make_float4(w.x * s2, w.y * s2, w.z * s2, w.w * s2);
        }
        if (doStats) {
            ls0 += w.x; ls1 += w.y; ls2 += w.z; ls3 += w.w;
            lq0 += w.x * w.x; lq1 += w.y * w.y; lq2 += w.z * w.z; lq3 += w.w * w.w;
        }
    }
    if (doStats) {
        int cb = sub * 8 + half * 4;
        atomicAdd(&ssum[cb + 0], ls0); atomicAdd(&ssum[cb + 1], ls1);
        atomicAdd(&ssum[cb + 2], ls2); atomicAdd(&ssum[cb + 3], ls3);
        atomicAdd(&ssq [cb + 0], lq0); atomicAdd(&ssq [cb + 1], lq1);
        atomicAdd(&ssq [cb + 2], lq2); atomicAdd(&ssq [cb + 3], lq3);
        __syncthreads();
        if (tid < D) { atomicAdd(&sum[tid], ssum[tid]); atomicAdd(&sq[tid], ssq[tid]); }
    }
}

__global__ void k_rel_renorm(float* __restrict__ rf, int M) {
    int w = (blockIdx.x * blockDim.x + threadIdx.x) >> 5;
    int lane = threadIdx.x & 31;
    if (w >= M) return;
    float* rowp = rf + (size_t)w * 384;
    float4 v[3];
    float tot = 0.f;
#pragma unroll
    for (int j = 0; j < 3; j++) {
        v[j] = ((float4*)rowp)[j * 32 + lane];
        tot += v[j].x * v[j].x + v[j].y * v[j].y + v[j].z * v[j].z + v[j].w * v[j].w;
    }
#pragma unroll
    for (int o = 16; o; o >>= 1) tot += __shfl_xor_sync(0xffffffffu, tot, o);
    float it = 1.f / fmaxf(sqrtf(tot), 1e-12f);
#pragma unroll
    for (int j = 0; j < 3; j++)
        ((float4*)rowp)[j * 32 + lane] =
            make_float4(v[j].x * it, v[j].y * it, v[j].z * it, v[j].w * it);
}

// =============================== host orchestration ===============================
// Streams/events created ONCE per process (first call = correctness run, before
// the pre-capture memory baseline) and reused — teardown returns to baseline.
static cudaStream_t s_sB = 0, s_sC = 0, s_sD = 0;
static cudaEvent_t s_ev[12] = {0};

extern "C" void kernel_launch(void* const* d_in, const int* in_sizes, int n_in,
                              void* d_out, int out_size) {
    const float* ent      = (const float*)d_in[0];
    const float* rel      = (const float*)d_in[1];
    const float* W_inv    = (const float*)d_in[2];
    const float* b_inv    = (const float*)d_in[3];
    const float* bn_gamma = (const float*)d_in[4];
    const float* bn_beta  = (const float*)d_in[5];
    const float* rel_W    = (const float*)d_in[6];
    const float* rel_b    = (const float*)d_in[7];
    const float* ent_W    = (const float*)d_in[8];
    const float* ent_b    = (const float*)d_in[9];
    const float* s_W      = (const float*)d_in[10];
    const float* s_b      = (const float*)d_in[11];
    const float* conv_Wg  = (const float*)d_in[12];
    const float* conv_bg  = (const float*)d_in[13];
    const float* sconv_Wg = (const float*)d_in[14];
    const float* sconv_bg = (const float*)d_in[15];
    const int*   ei       = (const int*)d_in[16];
    const int*   cei      = (const int*)d_in[17];
    const int*   attr     = (const int*)d_in[18];

    const int n = in_sizes[0] / D;        // 100000
    const int E = in_sizes[18];           // 800000
    const float invN = 1.f / (float)n;

    float* out = (float*)d_out;
    float* FE = out;                                   // [n, 640]
    float* RF = out + (size_t)n * 640;                 // [2000, 384]
    float* LE = RF + (size_t)RELN * 384;               // [n, 256]
    float* LR = LE + (size_t)n * 256;                  // [2000, 128]

    float *HA, *HB, *rA, *rB, *bp1, *bp2, *st, *ksc, *lesc;
    __half *Xh1, *Xh2, *G1, *G2, *G1b, *G2b;
    unsigned *W1hi, *W1lo, *W2hi, *W2lo;
    int *cnt1, *cnt2, *cur1, *cur2, *off1, *off2, *bs1, *bs2;
    int2 *eSA1, *eSA2;
    cudaGetSymbolAddress((void**)&Xh1, g_Xh1);
    cudaGetSymbolAddress((void**)&Xh2, g_Xh2);
    cudaGetSymbolAddress((void**)&HA,  g_HA);
    cudaGetSymbolAddress((void**)&HB,  g_HB);
    cudaGetSymbolAddress((void**)&rA,  g_relA);
    cudaGetSymbolAddress((void**)&rB,  g_relB);
    cudaGetSymbolAddress((void**)&G1,  g_G1);
    cudaGetSymbolAddress((void**)&G2,  g_G2);
    cudaGetSymbolAddress((void**)&G1b, g_G1b);
    cudaGetSymbolAddress((void**)&G2b, g_G2b);
    cudaGetSymbolAddress((void**)&W1hi, g_W1hi);
    cudaGetSymbolAddress((void**)&W1lo, g_W1lo);
    cudaGetSymbolAddress((void**)&W2hi, g_W2hi);
    cudaGetSymbolAddress((void**)&W2lo, g_W2lo);
    cudaGetSymbolAddress((void**)&bp1, g_bp1);
    cudaGetSymbolAddress((void**)&bp2, g_bp2);
    cudaGetSymbolAddress((void**)&st,  g_stats);
    cudaGetSymbolAddress((void**)&ksc, g_ksc);
    cudaGetSymbolAddress((void**)&lesc,g_lesc);
    cudaGetSymbolAddress((void**)&cnt1,g_cnt1);
    cudaGetSymbolAddress((void**)&cnt2,g_cnt2);
    cudaGetSymbolAddress((void**)&cur1,g_cur1);
    cudaGetSymbolAddress((void**)&cur2,g_cur2);
    cudaGetSymbolAddress((void**)&off1,g_off1);
    cudaGetSymbolAddress((void**)&off2,g_off2);
    cudaGetSymbolAddress((void**)&bs1, g_bs1);
    cudaGetSymbolAddress((void**)&bs2, g_bs2);
    cudaGetSymbolAddress((void**)&eSA1,g_eSA1);
    cudaGetSymbolAddress((void**)&eSA2,g_eSA2);

    float* stE  = st;
    float* stHA = st + 2 * D;
    float* stHB = st + 4 * D;

    cudaFuncSetAttribute(k_gemm_mma,  cudaFuncAttributeMaxDynamicSharedMemorySize, SMEM_MMA);
    cudaFuncSetAttribute(k_gemm_mma2, cudaFuncAttributeMaxDynamicSharedMemorySize, SMEM_MMA2);

    const int gemmGrid   = (n + 127) / 128;
    const int gathGrid   = 1024;
    const int edgeGrid   = (E + 255) / 256;
    const int nbScan     = (n + CHUNK - 1) / CHUNK;
    const int rnBigGrid  = (n * 32 + 255) / 256;
    const int rnRelGrid  = (RELN * 32 + 255) / 256;

    // ---- streams + events: create once, first call only (pre-capture) ----
    if (s_sB == 0) {
        cudaStreamCreateWithFlags(&s_sB, cudaStreamNonBlocking);
        cudaStreamCreateWithFlags(&s_sC, cudaStreamNonBlocking);
        cudaStreamCreateWithFlags(&s_sD, cudaStreamNonBlocking);
        for (int i = 0; i < 12; i++)
            cudaEventCreateWithFlags(&s_ev[i], cudaEventDisableTiming);
    }
    cudaStream_t sB = s_sB, sC = s_sC, sD = s_sD;
    cudaEvent_t eFork = s_ev[0], eH2 = s_ev[1], eScales = s_ev[2], eX = s_ev[3],
                eGate = s_ev[4], eRel = s_ev[5], eG1 = s_ev[6], eG2 = s_ev[7],
                eF2 = s_ev[8], eDend = s_ev[9], eCend = s_ev[10];

    // ---- fork ----
    cudaEventRecord(eFork, 0);
    cudaStreamWaitEvent(sB, eFork, 0);
    cudaStreamWaitEvent(sC, eFork, 0);
    cudaStreamWaitEvent(sD, eFork, 0);

    // ---- stream D: relation/gate chain (no deps, starts at t=0) ----
    cudaMemcpyAsync(rA, rel, (size_t)1000 * D * sizeof(float),
                    cudaMemcpyDeviceToDevice, sD);
    k_small_gemm<<<125, 128, 0, sD>>>(rel, W_inv, b_inv, rA + 1000 * D, 1000);
    k_rownorm<<<rnRelGrid, 256, 0, sD>>>(rA, RELN, RF, 384, nullptr, 0, nullptr);
    k_small_gemm<<<250, 128, 0, sD>>>(rA, rel_W, rel_b, rB, RELN);
    k_rownorm<<<rnRelGrid, 256, 0, sD>>>(rB, RELN, RF + 128, 384, nullptr, 0, nullptr);
    k_gate_gemm2<<<250, 128, 0, sD>>>(rB, conv_Wg, conv_bg, G1,
                                      sconv_Wg, sconv_bg, G2, RELN);
    cudaEventRecord(eGate, sD);
    k_small_gemm<<<250, 128, 0, sD>>>(rB, rel_W + D * D, rel_b + D, rA, RELN);
    k_rownorm<<<rnRelGrid, 256, 0, sD>>>(rA, RELN, RF + 256, 384, LR, 128, nullptr);
    k_gate_gemm2<<<250, 128, 0, sD>>>(rA, conv_Wg + D * D, conv_bg + D, G1b,
                                      sconv_Wg + D * D, sconv_bg + D, G2b, RELN);
    cudaEventRecord(eRel, sD);
    k_rel_renorm<<<rnRelGrid, 256, 0, sD>>>(RF, RELN);
    cudaEventRecord(eDend, sD);

    // ---- stream C: ent stats -> preps -> dual GEMM (no CSR dep) ----
    cudaMemsetAsync(st, 0, 6 * D * sizeof(float), sC);
    k_stats<<<512, 256, 0, sC>>>(ent, stE, stE + D, n);
    k_prep_wb<<<1, 128, 0, sC>>>(stE, stE + D, bn_gamma, bn_beta, ent_W, ent_b,
                                 W1hi, W1lo, bp1, invN);
    k_prep_wb<<<1, 128, 0, sC>>>(stE, stE + D, bn_gamma, bn_beta, s_W, s_b,
                                 W2hi, W2lo, bp2, invN);
    k_gemm_mma2<<<gemmGrid, 256, SMEM_MMA2, sC>>>(ent,
        (const uint4*)W1hi, (const uint4*)W1lo, bp1, Xh1,
        (const uint4*)W2hi, (const uint4*)W2lo, bp2, Xh2, n);
    cudaEventRecord(eX, sC);

    // ---- stream B: CSR graph2 ----
    cudaMemsetAsync(cnt2, 0, n * sizeof(int), sB);
    k_hist<<<edgeGrid, 256, 0, sB>>>(cei + E, cnt2, E);
    cudaEventRecord(eH2, sB);
    k_scan_sum<<<nbScan, CHUNK, 0, sB>>>(cnt2, bs2, n);
    k_scan_top<<<1, 256, 0, sB>>>(bs2, nbScan);
    k_scan_out<<<nbScan, CHUNK, 0, sB>>>(cnt2, bs2, off2, cur2, n, E);
    k_fill<<<edgeGrid, 256, 0, sB>>>(cei, cei + E, attr, cur2, eSA2, E);

    // ---- stream A (=0): CSR graph1 (scales right after hists) ----
    cudaMemsetAsync(cnt1, 0, n * sizeof(int), 0);
    k_hist<<<edgeGrid, 256, 0, 0>>>(ei + E, cnt1, E);
    cudaStreamWaitEvent(0, eH2, 0);
    k_scales<<<(n + 255) / 256, 256, 0, 0>>>(cnt1, cnt2, ksc, lesc, n);
    cudaEventRecord(eScales, 0);
    k_scan_sum<<<nbScan, CHUNK, 0, 0>>>(cnt1, bs1, n);
    k_scan_top<<<1, 256, 0, 0>>>(bs1, nbScan);
    k_scan_out<<<nbScan, CHUNK, 0, 0>>>(cnt1, bs1, off1, cur1, n, E);
    k_fill<<<edgeGrid, 256, 0, 0>>>(ei, ei + E, attr, cur1, eSA1, E);

    // block0 = ksc * normalize(ent) on C, overlapped with gathers
    cudaStreamWaitEvent(sC, eScales, 0);
    k_rownorm<<<rnBigGrid, 256, 0, sC>>>(ent, n, FE, 640, nullptr, 0, ksc);
    cudaEventRecord(eCend, sC);

    // ---- layer-0 gathers (A and B, concurrent) ----
    cudaStreamWaitEvent(0, eX, 0);
    cudaStreamWaitEvent(0, eGate, 0);
    k_gather<<<gathGrid, 256, 0, 0>>>(Xh1, G1, off1, eSA1, HA, FE + 256, 640, ksc,
                                      nullptr, nullptr, stHA, stHA + D, n);
    cudaEventRecord(eG1, 0);
    cudaStreamWaitEvent(sB, eX, 0);
    cudaStreamWaitEvent(sB, eGate, 0);
    cudaStreamWaitEvent(sB, eScales, 0);
    k_gather<<<gathGrid, 256, 0, sB>>>(Xh2, G2, off2, eSA2, HB, FE + 128, 640, ksc,
                                       nullptr, nullptr, stHB, stHB + D, n);
    cudaEventRecord(eG2, sB);

    // ---- layer-1 branch on A: HB path (needs gather2 done) ----
    cudaStreamWaitEvent(0, eG2, 0);
    k_prep_wb<<<1, 128, 0, 0>>>(stHB, stHB + D, bn_gamma + D, bn_beta + D,
                                ent_W + D * D, ent_b + D, W1hi, W1lo, bp1, invN);
    k_gemm_mma<<<gemmGrid, 256, SMEM_MMA, 0>>>(HB, (const uint4*)W1hi,
                                               (const uint4*)W1lo, bp1, Xh1, n);
    cudaStreamWaitEvent(0, eRel, 0);
    k_gather<<<gathGrid, 256, 0, 0>>>(Xh1, G1b, off1, eSA1, nullptr, FE + 512, 640,
                                      ksc, LE + 128, lesc, nullptr, nullptr, n);

    // ---- layer-1 branch on B: HA path (needs gather1 done) ----
    cudaStreamWaitEvent(sB, eG1, 0);
    k_prep_wb<<<1, 128, 0, sB>>>(stHA, stHA + D, bn_gamma + D, bn_beta + D,
                                 s_W + D * D, s_b + D, W2hi, W2lo, bp2, invN);
    k_gemm_mma<<<gemmGrid, 256, SMEM_MMA, sB>>>(HA, (const uint4*)W2hi,
                                                (const uint4*)W2lo, bp2, Xh2, n);
    cudaStreamWaitEvent(sB, eRel, 0);
    k_gather<<<gathGrid, 256, 0, sB>>>(Xh2, G2b, off2, eSA2, nullptr, FE + 384, 640,
                                       ksc, LE, lesc, nullptr, nullptr, n);
    cudaEventRecord(eF2, sB);

    // ---- join everything back onto the origin stream ----
    cudaStreamWaitEvent(0, eF2, 0);
    cudaStreamWaitEvent(0, eCend, 0);
    cudaStreamWaitEvent(0, eDend, 0);
}

// round 15
// speedup vs baseline: 1.0622x; 1.0622x over previous
#include <cuda_runtime.h>
#include <cuda_bf16.h>
#include <cuda_fp16.h>
#include <math.h>
#include <stdint.h>

#define D 128
#define NMAX 100000
#define EMAX 800000
#define RELN 2000
#define CHUNK 512
#define NB_MAX 256

// ---------------- static device scratch (no runtime allocation) ----------------
__device__ __align__(16) __half g_Xh1[NMAX * D];
__device__ __align__(16) __half g_Xh2[NMAX * D];
__device__ __align__(16) float g_HA[NMAX * D];
__device__ __align__(16) float g_HB[NMAX * D];
__device__ __align__(16) float g_relA[RELN * D];
__device__ __align__(16) float g_relB[RELN * D];
__device__ __align__(16) __half g_G1[RELN * D];
__device__ __align__(16) __half g_G2[RELN * D];
__device__ __align__(16) __half g_G1b[RELN * D];
__device__ __align__(16) __half g_G2b[RELN * D];
__device__ __align__(16) unsigned g_W1hi[D * 64];
__device__ __align__(16) unsigned g_W1lo[D * 64];
__device__ __align__(16) unsigned g_W2hi[D * 64];
__device__ __align__(16) unsigned g_W2lo[D * 64];
__device__ __align__(16) float g_bp1[D];
__device__ __align__(16) float g_bp2[D];
__device__ __align__(16) float g_stats[6 * D];
__device__ __align__(16) float g_ksc[NMAX];
__device__ __align__(16) float g_lesc[NMAX];
// CSR scratch (separate per graph so builds are stream-parallel)
__device__ int g_cnt1[NMAX], g_cnt2[NMAX];
__device__ int g_cur1[NMAX], g_cur2[NMAX];
__device__ int g_off1[NMAX + 1];
__device__ int g_off2[NMAX + 1];
__device__ int g_bs1[NB_MAX], g_bs2[NB_MAX];
__device__ __align__(8) int2 g_eSA1[EMAX];
__device__ __align__(8) int2 g_eSA2[EMAX];

// ================= CSR build =================
__global__ void k_hist(const int* __restrict__ dst, int* __restrict__ cnt, int E) {
    int e = blockIdx.x * blockDim.x + threadIdx.x;
    if (e < E) atomicAdd(&cnt[dst[e]], 1);
}

__global__ void k_scan_sum(const int* __restrict__ cnt, int* __restrict__ bs, int n) {
    __shared__ int sh[CHUNK];
    int t = threadIdx.x;
    int i = blockIdx.x * CHUNK + t;
    sh[t] = (i < n) ? cnt[i] : 0;
    __syncthreads();
#pragma unroll
    for (int o = CHUNK / 2; o; o >>= 1) {
        if (t < o) sh[t] += sh[t + o];
        __syncthreads();
    }
    if (t == 0) bs[blockIdx.x] = sh[0];
}

__global__ void k_scan_top(int* __restrict__ bs, int nb) {
    __shared__ int sh[256];
    int t = threadIdx.x;
    int v = (t < nb) ? bs[t] : 0;
    sh[t] = v;
    __syncthreads();
#pragma unroll
    for (int o = 1; o < 256; o <<= 1) {
        int x = (t >= o) ? sh[t - o] : 0;
        __syncthreads();
        sh[t] += x;
        __syncthreads();
    }
    if (t < nb) bs[t] = sh[t] - v;
}

__global__ void k_scan_out(const int* __restrict__ cnt, const int* __restrict__ bs,
                           int* __restrict__ off, int* __restrict__ cur, int n, int E) {
    __shared__ int sh[CHUNK];
    int t = threadIdx.x;
    int i = blockIdx.x * CHUNK + t;
    int v = (i < n) ? cnt[i] : 0;
    sh[t] = v;
    __syncthreads();
#pragma unroll
    for (int o = 1; o < CHUNK; o <<= 1) {
        int x = (t >= o) ? sh[t - o] : 0;
        __syncthreads();
        sh[t] += x;
        __syncthreads();
    }
    if (i < n) {
        int e = bs[blockIdx.x] + sh[t] - v;
        off[i] = e;
        cur[i] = e;
    }
    if (i == 0) off[n] = E;
}

__global__ void k_fill(const int* __restrict__ src, const int* __restrict__ dst,
                       const int* __restrict__ attr, int* __restrict__ cur,
                       int2* __restrict__ eSA, int E) {
    int e = blockIdx.x * blockDim.x + threadIdx.x;
    if (e >= E) return;
    int p = atomicAdd(&cur[dst[e]], 1);
    eSA[p] = make_int2(src[e], attr[e]);
}

// per-node output scales from histogram counts
__global__ void k_scales(const int* __restrict__ cnt1, const int* __restrict__ cnt2,
                         float* __restrict__ ksc, float* __restrict__ lesc, int n) {
    int v = blockIdx.x * blockDim.x + threadIdx.x;
    if (v >= n) return;
    int d1 = cnt1[v] > 0;
    int d2 = cnt2[v] > 0;
    ksc[v] = rsqrtf((float)(1 + 2 * d1 + 2 * d2));
    int k2 = d1 + d2;
    lesc[v] = k2 ? rsqrtf((float)k2) : 0.f;
}

// ---------------- small GEMM: C[M,128] = A @ W + b ----------------
__global__ void k_small_gemm(const float* __restrict__ A, const float* __restrict__ W,
                             const float* __restrict__ b, float* __restrict__ C, int M) {
    __shared__ float As[8][D];
    int r0 = blockIdx.x * 8;
    int c = threadIdx.x;
#pragma unroll
    for (int r = 0; r < 8; r++) {
        int rr = r0 + r;
        As[r][c] = (rr < M) ? A[(size_t)rr * D + c] : 0.f;
    }
    __syncthreads();
    float acc[8];
    float bias = b[c];
#pragma unroll
    for (int r = 0; r < 8; r++) acc[r] = bias;
    for (int k = 0; k < D; k++) {
        float w = W[k * D + c];
#pragma unroll
        for (int r = 0; r < 8; r++) acc[r] = fmaf(As[r][k], w, acc[r]);
    }
#pragma unroll
    for (int r = 0; r < 8; r++) {
        int rr = r0 + r;
        if (rr < M) C[(size_t)rr * D + c] = acc[r];
    }
}

// dual gate GEMM (fp16 output)
__global__ void k_gate_gemm2(const float* __restrict__ A,
                             const float* __restrict__ W1, const float* __restrict__ b1,
                             __half* __restrict__ C1,
                             const float* __restrict__ W2, const float* __restrict__ b2,
                             __half* __restrict__ C2, int M) {
    __shared__ float As[8][D];
    int r0 = blockIdx.x * 8;
    int c = threadIdx.x;
#pragma unroll
    for (int r = 0; r < 8; r++) {
        int rr = r0 + r;
        As[r][c] = (rr < M) ? A[(size_t)rr * D + c] : 0.f;
    }
    __syncthreads();
    float a1[8], a2[8];
    float bb1 = b1[c], bb2 = b2[c];
#pragma unroll
    for (int r = 0; r < 8; r++) { a1[r] = bb1; a2[r] = bb2; }
    for (int k = 0; k < D; k++) {
        float w1 = W1[k * D + c];
        float w2 = W2[k * D + c];
#pragma unroll
        for (int r = 0; r < 8; r++) {
            float av = As[r][k];
            a1[r] = fmaf(av, w1, a1[r]);
            a2[r] = fmaf(av, w2, a2[r]);
        }
    }
#pragma unroll
    for (int r = 0; r < 8; r++) {
        int rr = r0 + r;
        if (rr < M) {
            C1[(size_t)rr * D + c] = __float2half_rn(1.f / (1.f + expf(-a1[r])));
            C2[(size_t)rr * D + c] = __float2half_rn(1.f / (1.f + expf(-a2[r])));
        }
    }
}

// -------- fold BatchNorm into GEMM weights; emit W^T as bf16 hi/lo + bias --------
__global__ void k_prep_wb(const float* __restrict__ sum, const float* __restrict__ sq,
                          const float* __restrict__ gamma, const float* __restrict__ beta,
                          const float* __restrict__ W, const float* __restrict__ b,
                          unsigned* __restrict__ Whi, unsigned* __restrict__ Wlo,
                          float* __restrict__ bp, float invN) {
    __shared__ float sa[D], sc[D];
    int j = threadIdx.x;
    float m = sum[j] * invN;
    float v = sq[j] * invN - m * m;
    float a = rsqrtf(v + 1e-5f) * gamma[j];
    sa[j] = a;
    sc[j] = beta[j] - m * a;
    __syncthreads();
    float acc = b[j];
    for (int k = 0; k < D; k += 2) {
        float w0r = W[k * D + j];
        float w1r = W[(k + 1) * D + j];
        acc = fmaf(sc[k], w0r, acc);
        acc = fmaf(sc[k + 1], w1r, acc);
        float w0 = sa[k] * w0r;
        float w1 = sa[k + 1] * w1r;
        __nv_bfloat16 h0 = __float2bfloat16_rn(w0);
        __nv_bfloat16 h1 = __float2bfloat16_rn(w1);
        float r0 = w0 - __bfloat162float(h0);
        float r1 = w1 - __bfloat162float(h1);
        __nv_bfloat16 l0 = __float2bfloat16_rn(r0);
        __nv_bfloat16 l1 = __float2bfloat16_rn(r1);
        Whi[j * 64 + k / 2] = (unsigned)__bfloat16_as_ushort(h0) |
                              ((unsigned)__bfloat16_as_ushort(h1) << 16);
        Wlo[j * 64 + k / 2] = (unsigned)__bfloat16_as_ushort(l0) |
                              ((unsigned)__bfloat16_as_ushort(l1) << 16);
    }
    bp[j] = acc;
}

// ================ tensor-core GEMM via mma.sync (bf16 2-way split) ================
#define PADW 68
#define ROWB (PADW * 4)
#define T_BYTES (128 * ROWB)

__device__ __forceinline__ void split8(const float* x, uint4& hv, uint4& lv) {
    unsigned h[4], l[4];
#pragma unroll
    for (int i = 0; i < 4; i++) {
        float a = x[2 * i], b = x[2 * i + 1];
        __nv_bfloat16 ha = __float2bfloat16_rn(a);
        __nv_bfloat16 hb = __float2bfloat16_rn(b);
        float ra = a - __bfloat162float(ha);
        float rb = b - __bfloat162float(hb);
        __nv_bfloat16 la = __float2bfloat16_rn(ra);
        __nv_bfloat16 lb = __float2bfloat16_rn(rb);
        h[i] = (unsigned)__bfloat16_as_ushort(ha) | ((unsigned)__bfloat16_as_ushort(hb) << 16);
        l[i] = (unsigned)__bfloat16_as_ushort(la) | ((unsigned)__bfloat16_as_ushort(lb) << 16);
    }
    hv = make_uint4(h[0], h[1], h[2], h[3]);
    lv = make_uint4(l[0], l[1], l[2], l[3]);
}

__device__ __forceinline__ void mma16816(float* c, const uint32_t* a,
                                         uint32_t b0, uint32_t b1) {
    asm volatile(
        "mma.sync.aligned.m16n8k16.row.col.f32.bf16.bf16.f32 "
        "{%0,%1,%2,%3}, {%4,%5,%6,%7}, {%8,%9}, {%0,%1,%2,%3};"
        : "+f"(c[0]), "+f"(c[1]), "+f"(c[2]), "+f"(c[3])
        : "r"(a[0]), "r"(a[1]), "r"(a[2]), "r"(a[3]), "r"(b0), "r"(b1));
}

__device__ __forceinline__ void gemm_core(const char* sm, int offA_hi, int offA_lo,
                                          int offW_hi, int offW_lo,
                                          const float* sBias, __half* C,
                                          int rowBase, int M, int tid) {
    const int lane = tid & 31, wid = tid >> 5;
    const int gid = lane >> 2, tig = lane & 3;
    const int wr = wid & 3;
    const int wc = wid >> 2;

    float acc[2][8][4];
#pragma unroll
    for (int m = 0; m < 2; m++)
#pragma unroll
        for (int nt = 0; nt < 8; nt++)
#pragma unroll
            for (int j = 0; j < 4; j++) acc[m][nt][j] = 0.f;

    const uint32_t* Ahi = (const uint32_t*)(sm + offA_hi);
    const uint32_t* Alo = (const uint32_t*)(sm + offA_lo);
    const uint32_t* Whi = (const uint32_t*)(sm + offW_hi);
    const uint32_t* Wlo = (const uint32_t*)(sm + offW_lo);

#pragma unroll
    for (int p = 0; p < 3; p++) {
        const uint32_t* Aw = (p == 2) ? Alo : Ahi;
        const uint32_t* Bw = (p == 1) ? Wlo : Whi;
#pragma unroll
        for (int kc = 0; kc < 8; kc++) {
            int kw = kc * 8 + tig;
            uint32_t a[2][4];
#pragma unroll
            for (int m = 0; m < 2; m++) {
                int rb = wr * 32 + m * 16 + gid;
                a[m][0] = Aw[rb * PADW + kw];
                a[m][1] = Aw[(rb + 8) * PADW + kw];
                a[m][2] = Aw[rb * PADW + kw + 4];
                a[m][3] = Aw[(rb + 8) * PADW + kw + 4];
            }
#pragma unroll
            for (int nt = 0; nt < 8; nt++) {
                int nr = wc * 64 + nt * 8 + gid;
                uint32_t b0 = Bw[nr * PADW + kw];
                uint32_t b1 = Bw[nr * PADW + kw + 4];
                mma16816(acc[0][nt], a[0], b0, b1);
                mma16816(acc[1][nt], a[1], b0, b1);
            }
        }
    }
#pragma unroll
    for (int m = 0; m < 2; m++) {
        int row0 = rowBase + wr * 32 + m * 16 + gid;
#pragma unroll
        for (int nt = 0; nt < 8; nt++) {
            int col = wc * 64 + nt * 8 + 2 * tig;
            float bb0 = sBias[col], bb1 = sBias[col + 1];
            if (row0 < M) {
                __half2 o = make_half2(__float2half_rn(acc[m][nt][0] + bb0),
                                       __float2half_rn(acc[m][nt][1] + bb1));
                ((__half2*)C)[(size_t)row0 * 64 + (col >> 1)] = o;
            }
            if (row0 + 8 < M) {
                __half2 o = make_half2(__float2half_rn(acc[m][nt][2] + bb0),
                                       __float2half_rn(acc[m][nt][3] + bb1));
                ((__half2*)C)[(size_t)(row0 + 8) * 64 + (col >> 1)] = o;
            }
        }
    }
}

// ---- single-output GEMM (layer 1) ----
#define S_BIAS 0
#define S_AHI  512
#define S_ALO  (S_AHI + T_BYTES)
#define S_WHI  (S_ALO + T_BYTES)
#define S_WLO  (S_WHI + T_BYTES)
#define SMEM_MMA  (S_WLO + T_BYTES)            // 139776

__global__ __launch_bounds__(256, 1)
void k_gemm_mma(const float* __restrict__ A, const uint4* __restrict__ WhiG,
                const uint4* __restrict__ WloG, const float* __restrict__ bp,
                __half* __restrict__ C, int M) {
    extern __shared__ char sm2[];
    const int tid = threadIdx.x;
    const int rowBase = blockIdx.x * 128;
    if (tid < 128) ((float*)(sm2 + S_BIAS))[tid] = bp[tid];
#pragma unroll
    for (int i = 0; i < 8; i++) {
        int idx = tid + i * 256;
        int r = idx >> 4, q = idx & 15;
        ((uint4*)(sm2 + S_WHI))[r * 17 + q] = WhiG[idx];
        ((uint4*)(sm2 + S_WLO))[r * 17 + q] = WloG[idx];
    }
#pragma unroll
    for (int i = 0; i < 8; i++) {
        int idx = tid + i * 256;
        int r = idx >> 4, q = idx & 15;
        int grow = rowBase + r;
        float x[8] = {0.f, 0.f, 0.f, 0.f, 0.f, 0.f, 0.f, 0.f};
        if (grow < M) {
            float4 v0 = ((const float4*)A)[(size_t)grow * 32 + q * 2];
            float4 v1 = ((const float4*)A)[(size_t)grow * 32 + q * 2 + 1];
            x[0] = v0.x; x[1] = v0.y; x[2] = v0.z; x[3] = v0.w;
            x[4] = v1.x; x[5] = v1.y; x[6] = v1.z; x[7] = v1.w;
        }
        uint4 hv, lv;
        split8(x, hv, lv);
        ((uint4*)(sm2 + S_AHI))[r * 17 + q] = hv;
        ((uint4*)(sm2 + S_ALO))[r * 17 + q] = lv;
    }
    __syncthreads();
    gemm_core(sm2, S_AHI, S_ALO, S_WHI, S_WLO, (const float*)(sm2 + S_BIAS),
              C, rowBase, M, tid);
}

// ---- dual-output GEMM (layer 0: same A, two weight sets) ----
#define D_BIAS 0
#define D_AHI  1024
#define D_ALO  (D_AHI + T_BYTES)
#define D_W1HI (D_ALO + T_BYTES)
#define D_W1LO (D_W1HI + T_BYTES)
#define D_W2HI (D_W1LO + T_BYTES)
#define D_W2LO (D_W2HI + T_BYTES)
#define SMEM_MMA2 (D_W2LO + T_BYTES)           // 209920

__global__ __launch_bounds__(256, 1)
void k_gemm_mma2(const float* __restrict__ A,
                 const uint4* __restrict__ W1hiG, const uint4* __restrict__ W1loG,
                 const float* __restrict__ bp1, __half* __restrict__ C1,
                 const uint4* __restrict__ W2hiG, const uint4* __restrict__ W2loG,
                 const float* __restrict__ bp2, __half* __restrict__ C2, int M) {
    extern __shared__ char sm3[];
    const int tid = threadIdx.x;
    const int rowBase = blockIdx.x * 128;
    if (tid < 128) {
        ((float*)(sm3 + D_BIAS))[tid] = bp1[tid];
        ((float*)(sm3 + D_BIAS + 512))[tid] = bp2[tid];
    }
#pragma unroll
    for (int i = 0; i < 8; i++) {
        int idx = tid + i * 256;
        int r = idx >> 4, q = idx & 15;
        ((uint4*)(sm3 + D_W1HI))[r * 17 + q] = W1hiG[idx];
        ((uint4*)(sm3 + D_W1LO))[r * 17 + q] = W1loG[idx];
        ((uint4*)(sm3 + D_W2HI))[r * 17 + q] = W2hiG[idx];
        ((uint4*)(sm3 + D_W2LO))[r * 17 + q] = W2loG[idx];
    }
#pragma unroll
    for (int i = 0; i < 8; i++) {
        int idx = tid + i * 256;
        int r = idx >> 4, q = idx & 15;
        int grow = rowBase + r;
        float x[8] = {0.f, 0.f, 0.f, 0.f, 0.f, 0.f, 0.f, 0.f};
        if (grow < M) {
            float4 v0 = ((const float4*)A)[(size_t)grow * 32 + q * 2];
            float4 v1 = ((const float4*)A)[(size_t)grow * 32 + q * 2 + 1];
            x[0] = v0.x; x[1] = v0.y; x[2] = v0.z; x[3] = v0.w;
            x[4] = v1.x; x[5] = v1.y; x[6] = v1.z; x[7] = v1.w;
        }
        uint4 hv, lv;
        split8(x, hv, lv);
        ((uint4*)(sm3 + D_AHI))[r * 17 + q] = hv;
        ((uint4*)(sm3 + D_ALO))[r * 17 + q] = lv;
    }
    __syncthreads();
    gemm_core(sm3, D_AHI, D_ALO, D_W1HI, D_W1LO, (const float*)(sm3 + D_BIAS),
              C1, rowBase, M, tid);
    gemm_core(sm3, D_AHI, D_ALO, D_W2HI, D_W2LO, (const float*)(sm3 + D_BIAS + 512),
              C2, rowBase, M, tid);
}

// -------- column stats only (no write) --------
__global__ void k_stats(const float* __restrict__ src,
                        float* __restrict__ sum, float* __restrict__ sq, int n) {
    __shared__ float ssum[D], ssq[D];
    int tid = threadIdx.x;
    if (tid < D) { ssum[tid] = 0.f; ssq[tid] = 0.f; }
    __syncthreads();
    int lane = tid & 31;
    int warp = (blockIdx.x * blockDim.x + tid) >> 5;
    int nwarps = (gridDim.x * blockDim.x) >> 5;
    float4 ls = make_float4(0.f, 0.f, 0.f, 0.f);
    float4 lq = make_float4(0.f, 0.f, 0.f, 0.f);
    for (int row = warp; row < n; row += nwarps) {
        float4 v = ((const float4*)src)[(size_t)row * 32 + lane];
        ls.x += v.x; ls.y += v.y; ls.z += v.z; ls.w += v.w;
        lq.x += v.x * v.x; lq.y += v.y * v.y; lq.z += v.z * v.z; lq.w += v.w * v.w;
    }
    atomicAdd(&ssum[lane * 4 + 0], ls.x); atomicAdd(&ssum[lane * 4 + 1], ls.y);
    atomicAdd(&ssum[lane * 4 + 2], ls.z); atomicAdd(&ssum[lane * 4 + 3], ls.w);
    atomicAdd(&ssq [lane * 4 + 0], lq.x); atomicAdd(&ssq [lane * 4 + 1], lq.y);
    atomicAdd(&ssq [lane * 4 + 2], lq.z); atomicAdd(&ssq [lane * 4 + 3], lq.w);
    __syncthreads();
    if (tid < D) { atomicAdd(&sum[tid], ssum[tid]); atomicAdd(&sq[tid], ssq[tid]); }
}

// -------- row-normalize: dst = scale[row] * src/||src||  (scale nullptr -> 1) ----
__global__ void k_rownorm(const float* __restrict__ src, int M, float* __restrict__ dst,
                          int ldDst, float* __restrict__ dst2, int ldDst2,
                          const float* __restrict__ scale) {
    int w = (blockIdx.x * blockDim.x + threadIdx.x) >> 5;
    int lane = threadIdx.x & 31;
    if (w >= M) return;
    float4 v = ((const float4*)src)[(size_t)w * 32 + lane];
    float s = v.x * v.x + v.y * v.y + v.z * v.z + v.w * v.w;
#pragma unroll
    for (int o = 16; o; o >>= 1) s += __shfl_xor_sync(0xffffffffu, s, o);
    float sc = scale ? scale[w] : 1.f;
    float inv = sc / fmaxf(sqrtf(s), 1e-12f);
    float4 o4 = make_float4(v.x * inv, v.y * inv, v.z * inv, v.w * inv);
    ((float4*)(dst + (size_t)w * ldDst))[lane] = o4;
    if (dst2) ((float4*)(dst2 + (size_t)w * ldDst2))[lane] = o4;
}

// -------- CSR gather conv v2 (proven fastest): half-warp per edge, LDG.128,
//          4 edges per step, grid-stride node assignment --------
__device__ __forceinline__ void fma8(float* acc, uint4 g, uint4 x) {
    __half2* gh = (__half2*)&g;
    __half2* xh = (__half2*)&x;
#pragma unroll
    for (int i = 0; i < 4; i++) {
        float2 gf = __half22float2(gh[i]);
        float2 xf = __half22float2(xh[i]);
        acc[2 * i]     = fmaf(gf.x, xf.x, acc[2 * i]);
        acc[2 * i + 1] = fmaf(gf.y, xf.y, acc[2 * i + 1]);
    }
}

__global__ void k_gather(const __half* __restrict__ X, const __half* __restrict__ G,
                         const int* __restrict__ off, const int2* __restrict__ eSA,
                         float* __restrict__ rawH,
                         float* __restrict__ normDst, int ldNorm,
                         const float* __restrict__ ksc,
                         float* __restrict__ le, const float* __restrict__ lesc,
                         float* __restrict__ sum, float* __restrict__ sq, int n) {
    __shared__ float ssum[D], ssq[D];
    int tid = threadIdx.x;
    const bool doStats = (sum != nullptr);
    if (doStats) {
        if (tid < D) { ssum[tid] = 0.f; ssq[tid] = 0.f; }
        __syncthreads();
    }
    int lane = tid & 31;
    int sub = lane & 15, half = lane >> 4;
    int warp = (blockIdx.x * blockDim.x + tid) >> 5;
    int nwarps = (gridDim.x * blockDim.x) >> 5;
    const uint4* G4 = (const uint4*)G;
    const uint4* X4 = (const uint4*)X;
    float ls0 = 0.f, ls1 = 0.f, ls2 = 0.f, ls3 = 0.f;
    float lq0 = 0.f, lq1 = 0.f, lq2 = 0.f, lq3 = 0.f;

    for (int v = warp; v < n; v += nwarps) {
        int b0 = off[v], b1 = off[v + 1];
        float acc[8] = {0.f, 0.f, 0.f, 0.f, 0.f, 0.f, 0.f, 0.f};
        for (int base = b0; base < b1; base += 32) {
            int cnt = min(32, b1 - base);
            int2 sa = make_int2(0, 0);
            if (lane < cnt) sa = eSA[base + lane];
            int j = 0;
            for (; j + 4 <= cnt; j += 4) {
                int e0 = j + half, e1 = j + 2 + half;
                int s0 = __shfl_sync(0xffffffffu, sa.x, e0);
                int a0 = __shfl_sync(0xffffffffu, sa.y, e0);
                int s1 = __shfl_sync(0xffffffffu, sa.x, e1);
                int a1 = __shfl_sync(0xffffffffu, sa.y, e1);
                uint4 g0 = G4[a0 * 16 + sub];
                uint4 x0 = X4[(size_t)s0 * 16 + sub];
                uint4 g1 = G4[a1 * 16 + sub];
                uint4 x1 = X4[(size_t)s1 * 16 + sub];
                fma8(acc, g0, x0);
                fma8(acc, g1, x1);
            }
            for (; j < cnt; j += 2) {
                int e = min(j + half, cnt - 1);
                int s0 = __shfl_sync(0xffffffffu, sa.x, e);
                int a0 = __shfl_sync(0xffffffffu, sa.y, e);
                if (j + half < cnt) {
                    uint4 g = G4[a0 * 16 + sub];
                    uint4 x = X4[(size_t)s0 * 16 + sub];
                    fma8(acc, g, x);
                }
            }
        }
        // merge the two edge-halves (duplicate full row in both halves)
#pragma unroll
        for (int k = 0; k < 8; k++)
            acc[k] += __shfl_xor_sync(0xffffffffu, acc[k], 16);
        // row norm: reduce within the 16-lane half (covers all 128 cols)
        float ns = 0.f;
#pragma unroll
        for (int k = 0; k < 8; k++) ns += acc[k] * acc[k];
#pragma unroll
        for (int o = 1; o <= 8; o <<= 1) ns += __shfl_xor_sync(0xffffffffu, ns, o);
        float invB = 1.f / fmaxf(sqrtf(ns), 1e-12f);
        // this lane writes one float4: cols sub*8 + half*4 + [0,4)
        float4 w = make_float4(acc[half * 4 + 0], acc[half * 4 + 1],
                               acc[half * 4 + 2], acc[half * 4 + 3]);
        int q = sub * 2 + half;
        if (rawH) ((float4*)rawH)[(size_t)v * 32 + q] = w;
        float s1v = invB * ksc[v];
        ((float4*)(normDst + (size_t)v * ldNorm))[q] =
            make_float4(w.x * s1v, w.y * s1v, w.z * s1v, w.w * s1v);
        if (le) {
            float s2 = invB * lesc[v];
            ((float4*)(le + (size_t)v * 256))[q] =
                make_float4(w.x * s2, w.y * s2, w.z * s2, w.w * s2);
        }
        if (doStats) {
            ls0 += w.x; ls1 += w.y; ls2 += w.z; ls3 += w.w;
            lq0 += w.x * w.x; lq1 += w.y * w.y; lq2 += w.z * w.z; lq3 += w.w * w.w;
        }
    }
    if (doStats) {
        int cb = sub * 8 + half * 4;
        atomicAdd(&ssum[cb + 0], ls0); atomicAdd(&ssum[cb + 1], ls1);
        atomicAdd(&ssum[cb + 2], ls2); atomicAdd(&ssum[cb + 3], ls3);
        atomicAdd(&ssq [cb + 0], lq0); atomicAdd(&ssq [cb + 1], lq1);
        atomicAdd(&ssq [cb + 2], lq2); atomicAdd(&ssq [cb + 3], lq3);
        __syncthreads();
        if (tid < D) { atomicAdd(&sum[tid], ssum[tid]); atomicAdd(&sq[tid], ssq[tid]); }
    }
}

__global__ void k_rel_renorm(float* __restrict__ rf, int M) {
    int w = (blockIdx.x * blockDim.x + threadIdx.x) >> 5;
    int lane = threadIdx.x & 31;
    if (w >= M) return;
    float* rowp = rf + (size_t)w * 384;
    float4 v[3];
    float tot = 0.f;
#pragma unroll
    for (int j = 0; j < 3; j++) {
        v[j] = ((float4*)rowp)[j * 32 + lane];
        tot += v[j].x * v[j].x + v[j].y * v[j].y + v[j].z * v[j].z + v[j].w * v[j].w;
    }
#pragma unroll
    for (int o = 16; o; o >>= 1) tot += __shfl_xor_sync(0xffffffffu, tot, o);
    float it = 1.f / fmaxf(sqrtf(tot), 1e-12f);
#pragma unroll
    for (int j = 0; j < 3; j++)
        ((float4*)rowp)[j * 32 + lane] =
            make_float4(v[j].x * it, v[j].y * it, v[j].z * it, v[j].w * it);
}

// =============================== host orchestration ===============================
// Streams/events created ONCE per process (first call = correctness run, before
// the pre-capture memory baseline) and reused — teardown returns to baseline.
static cudaStream_t s_sB = 0, s_sC = 0, s_sD = 0;
static cudaEvent_t s_ev[12] = {0};

extern "C" void kernel_launch(void* const* d_in, const int* in_sizes, int n_in,
                              void* d_out, int out_size) {
    const float* ent      = (const float*)d_in[0];
    const float* rel      = (const float*)d_in[1];
    const float* W_inv    = (const float*)d_in[2];
    const float* b_inv    = (const float*)d_in[3];
    const float* bn_gamma = (const float*)d_in[4];
    const float* bn_beta  = (const float*)d_in[5];
    const float* rel_W    = (const float*)d_in[6];
    const float* rel_b    = (const float*)d_in[7];
    const float* ent_W    = (const float*)d_in[8];
    const float* ent_b    = (const float*)d_in[9];
    const float* s_W      = (const float*)d_in[10];
    const float* s_b      = (const float*)d_in[11];
    const float* conv_Wg  = (const float*)d_in[12];
    const float* conv_bg  = (const float*)d_in[13];
    const float* sconv_Wg = (const float*)d_in[14];
    const float* sconv_bg = (const float*)d_in[15];
    const int*   ei       = (const int*)d_in[16];
    const int*   cei      = (const int*)d_in[17];
    const int*   attr     = (const int*)d_in[18];

    const int n = in_sizes[0] / D;        // 100000
    const int E = in_sizes[18];           // 800000
    const float invN = 1.f / (float)n;

    float* out = (float*)d_out;
    float* FE = out;                                   // [n, 640]
    float* RF = out + (size_t)n * 640;                 // [2000, 384]
    float* LE = RF + (size_t)RELN * 384;               // [n, 256]
    float* LR = LE + (size_t)n * 256;                  // [2000, 128]

    float *HA, *HB, *rA, *rB, *bp1, *bp2, *st, *ksc, *lesc;
    __half *Xh1, *Xh2, *G1, *G2, *G1b, *G2b;
    unsigned *W1hi, *W1lo, *W2hi, *W2lo;
    int *cnt1, *cnt2, *cur1, *cur2, *off1, *off2, *bs1, *bs2;
    int2 *eSA1, *eSA2;
    cudaGetSymbolAddress((void**)&Xh1, g_Xh1);
    cudaGetSymbolAddress((void**)&Xh2, g_Xh2);
    cudaGetSymbolAddress((void**)&HA,  g_HA);
    cudaGetSymbolAddress((void**)&HB,  g_HB);
    cudaGetSymbolAddress((void**)&rA,  g_relA);
    cudaGetSymbolAddress((void**)&rB,  g_relB);
    cudaGetSymbolAddress((void**)&G1,  g_G1);
    cudaGetSymbolAddress((void**)&G2,  g_G2);
    cudaGetSymbolAddress((void**)&G1b, g_G1b);
    cudaGetSymbolAddress((void**)&G2b, g_G2b);
    cudaGetSymbolAddress((void**)&W1hi, g_W1hi);
    cudaGetSymbolAddress((void**)&W1lo, g_W1lo);
    cudaGetSymbolAddress((void**)&W2hi, g_W2hi);
    cudaGetSymbolAddress((void**)&W2lo, g_W2lo);
    cudaGetSymbolAddress((void**)&bp1, g_bp1);
    cudaGetSymbolAddress((void**)&bp2, g_bp2);
    cudaGetSymbolAddress((void**)&st,  g_stats);
    cudaGetSymbolAddress((void**)&ksc, g_ksc);
    cudaGetSymbolAddress((void**)&lesc,g_lesc);
    cudaGetSymbolAddress((void**)&cnt1,g_cnt1);
    cudaGetSymbolAddress((void**)&cnt2,g_cnt2);
    cudaGetSymbolAddress((void**)&cur1,g_cur1);
    cudaGetSymbolAddress((void**)&cur2,g_cur2);
    cudaGetSymbolAddress((void**)&off1,g_off1);
    cudaGetSymbolAddress((void**)&off2,g_off2);
    cudaGetSymbolAddress((void**)&bs1, g_bs1);
    cudaGetSymbolAddress((void**)&bs2, g_bs2);
    cudaGetSymbolAddress((void**)&eSA1,g_eSA1);
    cudaGetSymbolAddress((void**)&eSA2,g_eSA2);

    float* stE  = st;
    float* stHA = st + 2 * D;
    float* stHB = st + 4 * D;

    cudaFuncSetAttribute(k_gemm_mma,  cudaFuncAttributeMaxDynamicSharedMemorySize, SMEM_MMA);
    cudaFuncSetAttribute(k_gemm_mma2, cudaFuncAttributeMaxDynamicSharedMemorySize, SMEM_MMA2);

    const int gemmGrid   = (n + 127) / 128;
    const int gathGrid   = 2048;
    const int edgeGrid   = (E + 255) / 256;
    const int nbScan     = (n + CHUNK - 1) / CHUNK;
    const int rnBigGrid  = (n * 32 + 255) / 256;
    const int rnRelGrid  = (RELN * 32 + 255) / 256;

    // ---- streams + events: create once, first call only (pre-capture) ----
    if (s_sB == 0) {
        cudaStreamCreateWithFlags(&s_sB, cudaStreamNonBlocking);
        cudaStreamCreateWithFlags(&s_sC, cudaStreamNonBlocking);
        cudaStreamCreateWithFlags(&s_sD, cudaStreamNonBlocking);
        for (int i = 0; i < 12; i++)
            cudaEventCreateWithFlags(&s_ev[i], cudaEventDisableTiming);
    }
    cudaStream_t sB = s_sB, sC = s_sC, sD = s_sD;
    cudaEvent_t eFork = s_ev[0], eH2 = s_ev[1], eScales = s_ev[2], eX = s_ev[3],
                eGate = s_ev[4], eRel = s_ev[5], eG1 = s_ev[6], eG2 = s_ev[7],
                eF2 = s_ev[8], eDend = s_ev[9], eCend = s_ev[10];

    // ---- fork ----
    cudaEventRecord(eFork, 0);
    cudaStreamWaitEvent(sB, eFork, 0);
    cudaStreamWaitEvent(sC, eFork, 0);
    cudaStreamWaitEvent(sD, eFork, 0);

    // ---- stream D: relation/gate chain (no deps, starts at t=0) ----
    cudaMemcpyAsync(rA, rel, (size_t)1000 * D * sizeof(float),
                    cudaMemcpyDeviceToDevice, sD);
    k_small_gemm<<<125, 128, 0, sD>>>(rel, W_inv, b_inv, rA + 1000 * D, 1000);
    k_rownorm<<<rnRelGrid, 256, 0, sD>>>(rA, RELN, RF, 384, nullptr, 0, nullptr);
    k_small_gemm<<<250, 128, 0, sD>>>(rA, rel_W, rel_b, rB, RELN);
    k_rownorm<<<rnRelGrid, 256, 0, sD>>>(rB, RELN, RF + 128, 384, nullptr, 0, nullptr);
    k_gate_gemm2<<<250, 128, 0, sD>>>(rB, conv_Wg, conv_bg, G1,
                                      sconv_Wg, sconv_bg, G2, RELN);
    cudaEventRecord(eGate, sD);
    k_small_gemm<<<250, 128, 0, sD>>>(rB, rel_W + D * D, rel_b + D, rA, RELN);
    k_rownorm<<<rnRelGrid, 256, 0, sD>>>(rA, RELN, RF + 256, 384, LR, 128, nullptr);
    k_gate_gemm2<<<250, 128, 0, sD>>>(rA, conv_Wg + D * D, conv_bg + D, G1b,
                                      sconv_Wg + D * D, sconv_bg + D, G2b, RELN);
    cudaEventRecord(eRel, sD);
    k_rel_renorm<<<rnRelGrid, 256, 0, sD>>>(RF, RELN);
    cudaEventRecord(eDend, sD);

    // ---- stream C: ent stats -> preps -> dual GEMM (no CSR dep) ----
    cudaMemsetAsync(st, 0, 6 * D * sizeof(float), sC);
    k_stats<<<512, 256, 0, sC>>>(ent, stE, stE + D, n);
    k_prep_wb<<<1, 128, 0, sC>>>(stE, stE + D, bn_gamma, bn_beta, ent_W, ent_b,
                                 W1hi, W1lo, bp1, invN);
    k_prep_wb<<<1, 128, 0, sC>>>(stE, stE + D, bn_gamma, bn_beta, s_W, s_b,
                                 W2hi, W2lo, bp2, invN);
    k_gemm_mma2<<<gemmGrid, 256, SMEM_MMA2, sC>>>(ent,
        (const uint4*)W1hi, (const uint4*)W1lo, bp1, Xh1,
        (const uint4*)W2hi, (const uint4*)W2lo, bp2, Xh2, n);
    cudaEventRecord(eX, sC);

    // ---- stream B: CSR graph2 ----
    cudaMemsetAsync(cnt2, 0, n * sizeof(int), sB);
    k_hist<<<edgeGrid, 256, 0, sB>>>(cei + E, cnt2, E);
    cudaEventRecord(eH2, sB);
    k_scan_sum<<<nbScan, CHUNK, 0, sB>>>(cnt2, bs2, n);
    k_scan_top<<<1, 256, 0, sB>>>(bs2, nbScan);
    k_scan_out<<<nbScan, CHUNK, 0, sB>>>(cnt2, bs2, off2, cur2, n, E);
    k_fill<<<edgeGrid, 256, 0, sB>>>(cei, cei + E, attr, cur2, eSA2, E);

    // ---- stream A (=0): CSR graph1 (scales right after hists) ----
    cudaMemsetAsync(cnt1, 0, n * sizeof(int), 0);
    k_hist<<<edgeGrid, 256, 0, 0>>>(ei + E, cnt1, E);
    cudaStreamWaitEvent(0, eH2, 0);
    k_scales<<<(n + 255) / 256, 256, 0, 0>>>(cnt1, cnt2, ksc, lesc, n);
    cudaEventRecord(eScales, 0);
    k_scan_sum<<<nbScan, CHUNK, 0, 0>>>(cnt1, bs1, n);
    k_scan_top<<<1, 256, 0, 0>>>(bs1, nbScan);
    k_scan_out<<<nbScan, CHUNK, 0, 0>>>(cnt1, bs1, off1, cur1, n, E);
    k_fill<<<edgeGrid, 256, 0, 0>>>(ei, ei + E, attr, cur1, eSA1, E);

    // block0 = ksc * normalize(ent) on C, overlapped with gathers
    cudaStreamWaitEvent(sC, eScales, 0);
    k_rownorm<<<rnBigGrid, 256, 0, sC>>>(ent, n, FE, 640, nullptr, 0, ksc);
    cudaEventRecord(eCend, sC);

    // ---- layer-0 gathers (A and B, concurrent) ----
    cudaStreamWaitEvent(0, eX, 0);
    cudaStreamWaitEvent(0, eGate, 0);
    k_gather<<<gathGrid, 256, 0, 0>>>(Xh1, G1, off1, eSA1, HA, FE + 256, 640, ksc,
                                      nullptr, nullptr, stHA, stHA + D, n);
    cudaEventRecord(eG1, 0);
    cudaStreamWaitEvent(sB, eX, 0);
    cudaStreamWaitEvent(sB, eGate, 0);
    cudaStreamWaitEvent(sB, eScales, 0);
    k_gather<<<gathGrid, 256, 0, sB>>>(Xh2, G2, off2, eSA2, HB, FE + 128, 640, ksc,
                                       nullptr, nullptr, stHB, stHB + D, n);
    cudaEventRecord(eG2, sB);

    // ---- layer-1 branch on A: HB path (needs gather2 done) ----
    cudaStreamWaitEvent(0, eG2, 0);
    k_prep_wb<<<1, 128, 0, 0>>>(stHB, stHB + D, bn_gamma + D, bn_beta + D,
                                ent_W + D * D, ent_b + D, W1hi, W1lo, bp1, invN);
    k_gemm_mma<<<gemmGrid, 256, SMEM_MMA, 0>>>(HB, (const uint4*)W1hi,
                                               (const uint4*)W1lo, bp1, Xh1, n);
    cudaStreamWaitEvent(0, eRel, 0);
    k_gather<<<gathGrid, 256, 0, 0>>>(Xh1, G1b, off1, eSA1, nullptr, FE + 512, 640,
                                      ksc, LE + 128, lesc, nullptr, nullptr, n);

    // ---- layer-1 branch on B: HA path (needs gather1 done) ----
    cudaStreamWaitEvent(sB, eG1, 0);
    k_prep_wb<<<1, 128, 0, sB>>>(stHA, stHA + D, bn_gamma + D, bn_beta + D,
                                 s_W + D * D, s_b + D, W2hi, W2lo, bp2, invN);
    k_gemm_mma<<<gemmGrid, 256, SMEM_MMA, sB>>>(HA, (const uint4*)W2hi,
                                                (const uint4*)W2lo, bp2, Xh2, n);
    cudaStreamWaitEvent(sB, eRel, 0);
    k_gather<<<gathGrid, 256, 0, sB>>>(Xh2, G2b, off2, eSA2, nullptr, FE + 384, 640,
                                       ksc, LE, lesc, nullptr, nullptr, n);
    cudaEventRecord(eF2, sB);

    // ---- join everything back onto the origin stream ----
    cudaStreamWaitEvent(0, eF2, 0);
    cudaStreamWaitEvent(0, eCend, 0);
    cudaStreamWaitEvent(0, eDend, 0);
}

// round 17
// speedup vs baseline: 1.0847x; 1.0212x over previous
#include <cuda_runtime.h>
#include <cuda_bf16.h>
#include <cuda_fp16.h>
#include <math.h>
#include <stdint.h>

#define D 128
#define NMAX 100000
#define EMAX 800000
#define RELN 2000
#define CHUNK 512
#define NB_MAX 256

// ---------------- static device scratch (no runtime allocation) ----------------
__device__ __align__(16) __half g_Xh1[NMAX * D];
__device__ __align__(16) __half g_Xh2[NMAX * D];
__device__ __align__(16) float g_HA[NMAX * D];
__device__ __align__(16) float g_HB[NMAX * D];
__device__ __align__(16) float g_relA[RELN * D];
__device__ __align__(16) float g_relB[RELN * D];
__device__ __align__(16) __half g_G1[RELN * D];
__device__ __align__(16) __half g_G2[RELN * D];
__device__ __align__(16) __half g_G1b[RELN * D];
__device__ __align__(16) __half g_G2b[RELN * D];
__device__ __align__(16) unsigned g_W1hi[D * 64];
__device__ __align__(16) unsigned g_W1lo[D * 64];
__device__ __align__(16) unsigned g_W2hi[D * 64];
__device__ __align__(16) unsigned g_W2lo[D * 64];
__device__ __align__(16) float g_bp1[D];
__device__ __align__(16) float g_bp2[D];
__device__ __align__(16) float g_stats[6 * D];
__device__ __align__(16) float g_ksc[NMAX];
__device__ __align__(16) float g_lesc[NMAX];
// CSR scratch (separate per graph so builds are stream-parallel)
__device__ int g_cnt1[NMAX], g_cnt2[NMAX];
__device__ int g_cur1[NMAX], g_cur2[NMAX];
__device__ int g_off1[NMAX + 1];
__device__ int g_off2[NMAX + 1];
__device__ int g_bs1[NB_MAX], g_bs2[NB_MAX];
__device__ __align__(8) int2 g_eSA1[EMAX];
__device__ __align__(8) int2 g_eSA2[EMAX];

// ================= CSR build =================
__global__ void k_hist(const int* __restrict__ dst, int* __restrict__ cnt, int E) {
    int e = blockIdx.x * blockDim.x + threadIdx.x;
    if (e < E) atomicAdd(&cnt[dst[e]], 1);
}

__global__ void k_scan_sum(const int* __restrict__ cnt, int* __restrict__ bs, int n) {
    __shared__ int sh[CHUNK];
    int t = threadIdx.x;
    int i = blockIdx.x * CHUNK + t;
    sh[t] = (i < n) ? cnt[i] : 0;
    __syncthreads();
#pragma unroll
    for (int o = CHUNK / 2; o; o >>= 1) {
        if (t < o) sh[t] += sh[t + o];
        __syncthreads();
    }
    if (t == 0) bs[blockIdx.x] = sh[0];
}

__global__ void k_scan_top(int* __restrict__ bs, int nb) {
    __shared__ int sh[256];
    int t = threadIdx.x;
    int v = (t < nb) ? bs[t] : 0;
    sh[t] = v;
    __syncthreads();
#pragma unroll
    for (int o = 1; o < 256; o <<= 1) {
        int x = (t >= o) ? sh[t - o] : 0;
        __syncthreads();
        sh[t] += x;
        __syncthreads();
    }
    if (t < nb) bs[t] = sh[t] - v;
}

__global__ void k_scan_out(const int* __restrict__ cnt, const int* __restrict__ bs,
                           int* __restrict__ off, int* __restrict__ cur, int n, int E) {
    __shared__ int sh[CHUNK];
    int t = threadIdx.x;
    int i = blockIdx.x * CHUNK + t;
    int v = (i < n) ? cnt[i] : 0;
    sh[t] = v;
    __syncthreads();
#pragma unroll
    for (int o = 1; o < CHUNK; o <<= 1) {
        int x = (t >= o) ? sh[t - o] : 0;
        __syncthreads();
        sh[t] += x;
        __syncthreads();
    }
    if (i < n) {
        int e = bs[blockIdx.x] + sh[t] - v;
        off[i] = e;
        cur[i] = e;
    }
    if (i == 0) off[n] = E;
}

__global__ void k_fill(const int* __restrict__ src, const int* __restrict__ dst,
                       const int* __restrict__ attr, int* __restrict__ cur,
                       int2* __restrict__ eSA, int E) {
    int e = blockIdx.x * blockDim.x + threadIdx.x;
    if (e >= E) return;
    int p = atomicAdd(&cur[dst[e]], 1);
    eSA[p] = make_int2(src[e], attr[e]);
}

// per-node output scales from histogram counts
__global__ void k_scales(const int* __restrict__ cnt1, const int* __restrict__ cnt2,
                         float* __restrict__ ksc, float* __restrict__ lesc, int n) {
    int v = blockIdx.x * blockDim.x + threadIdx.x;
    if (v >= n) return;
    int d1 = cnt1[v] > 0;
    int d2 = cnt2[v] > 0;
    ksc[v] = rsqrtf((float)(1 + 2 * d1 + 2 * d2));
    int k2 = d1 + d2;
    lesc[v] = k2 ? rsqrtf((float)k2) : 0.f;
}

// ---------------- small GEMM: C[M,128] = A @ W + b ----------------
__global__ void k_small_gemm(const float* __restrict__ A, const float* __restrict__ W,
                             const float* __restrict__ b, float* __restrict__ C, int M) {
    __shared__ float As[8][D];
    int r0 = blockIdx.x * 8;
    int c = threadIdx.x;
#pragma unroll
    for (int r = 0; r < 8; r++) {
        int rr = r0 + r;
        As[r][c] = (rr < M) ? A[(size_t)rr * D + c] : 0.f;
    }
    __syncthreads();
    float acc[8];
    float bias = b[c];
#pragma unroll
    for (int r = 0; r < 8; r++) acc[r] = bias;
    for (int k = 0; k < D; k++) {
        float w = W[k * D + c];
#pragma unroll
        for (int r = 0; r < 8; r++) acc[r] = fmaf(As[r][k], w, acc[r]);
    }
#pragma unroll
    for (int r = 0; r < 8; r++) {
        int rr = r0 + r;
        if (rr < M) C[(size_t)rr * D + c] = acc[r];
    }
}

// dual gate GEMM (fp16 output)
__global__ void k_gate_gemm2(const float* __restrict__ A,
                             const float* __restrict__ W1, const float* __restrict__ b1,
                             __half* __restrict__ C1,
                             const float* __restrict__ W2, const float* __restrict__ b2,
                             __half* __restrict__ C2, int M) {
    __shared__ float As[8][D];
    int r0 = blockIdx.x * 8;
    int c = threadIdx.x;
#pragma unroll
    for (int r = 0; r < 8; r++) {
        int rr = r0 + r;
        As[r][c] = (rr < M) ? A[(size_t)rr * D + c] : 0.f;
    }
    __syncthreads();
    float a1[8], a2[8];
    float bb1 = b1[c], bb2 = b2[c];
#pragma unroll
    for (int r = 0; r < 8; r++) { a1[r] = bb1; a2[r] = bb2; }
    for (int k = 0; k < D; k++) {
        float w1 = W1[k * D + c];
        float w2 = W2[k * D + c];
#pragma unroll
        for (int r = 0; r < 8; r++) {
            float av = As[r][k];
            a1[r] = fmaf(av, w1, a1[r]);
            a2[r] = fmaf(av, w2, a2[r]);
        }
    }
#pragma unroll
    for (int r = 0; r < 8; r++) {
        int rr = r0 + r;
        if (rr < M) {
            C1[(size_t)rr * D + c] = __float2half_rn(1.f / (1.f + expf(-a1[r])));
            C2[(size_t)rr * D + c] = __float2half_rn(1.f / (1.f + expf(-a2[r])));
        }
    }
}

// -------- fold BatchNorm into GEMM weights; emit W^T as bf16 hi/lo + bias --------
__global__ void k_prep_wb(const float* __restrict__ sum, const float* __restrict__ sq,
                          const float* __restrict__ gamma, const float* __restrict__ beta,
                          const float* __restrict__ W, const float* __restrict__ b,
                          unsigned* __restrict__ Whi, unsigned* __restrict__ Wlo,
                          float* __restrict__ bp, float invN) {
    __shared__ float sa[D], sc[D];
    int j = threadIdx.x;
    float m = sum[j] * invN;
    float v = sq[j] * invN - m * m;
    float a = rsqrtf(v + 1e-5f) * gamma[j];
    sa[j] = a;
    sc[j] = beta[j] - m * a;
    __syncthreads();
    float acc = b[j];
    for (int k = 0; k < D; k += 2) {
        float w0r = W[k * D + j];
        float w1r = W[(k + 1) * D + j];
        acc = fmaf(sc[k], w0r, acc);
        acc = fmaf(sc[k + 1], w1r, acc);
        float w0 = sa[k] * w0r;
        float w1 = sa[k + 1] * w1r;
        __nv_bfloat16 h0 = __float2bfloat16_rn(w0);
        __nv_bfloat16 h1 = __float2bfloat16_rn(w1);
        float r0 = w0 - __bfloat162float(h0);
        float r1 = w1 - __bfloat162float(h1);
        __nv_bfloat16 l0 = __float2bfloat16_rn(r0);
        __nv_bfloat16 l1 = __float2bfloat16_rn(r1);
        Whi[j * 64 + k / 2] = (unsigned)__bfloat16_as_ushort(h0) |
                              ((unsigned)__bfloat16_as_ushort(h1) << 16);
        Wlo[j * 64 + k / 2] = (unsigned)__bfloat16_as_ushort(l0) |
                              ((unsigned)__bfloat16_as_ushort(l1) << 16);
    }
    bp[j] = acc;
}

// ================ tensor-core GEMM via mma.sync (bf16 2-way split) ================
#define PADW 68
#define ROWB (PADW * 4)
#define T_BYTES (128 * ROWB)

__device__ __forceinline__ void split8(const float* x, uint4& hv, uint4& lv) {
    unsigned h[4], l[4];
#pragma unroll
    for (int i = 0; i < 4; i++) {
        float a = x[2 * i], b = x[2 * i + 1];
        __nv_bfloat16 ha = __float2bfloat16_rn(a);
        __nv_bfloat16 hb = __float2bfloat16_rn(b);
        float ra = a - __bfloat162float(ha);
        float rb = b - __bfloat162float(hb);
        __nv_bfloat16 la = __float2bfloat16_rn(ra);
        __nv_bfloat16 lb = __float2bfloat16_rn(rb);
        h[i] = (unsigned)__bfloat16_as_ushort(ha) | ((unsigned)__bfloat16_as_ushort(hb) << 16);
        l[i] = (unsigned)__bfloat16_as_ushort(la) | ((unsigned)__bfloat16_as_ushort(lb) << 16);
    }
    hv = make_uint4(h[0], h[1], h[2], h[3]);
    lv = make_uint4(l[0], l[1], l[2], l[3]);
}

__device__ __forceinline__ void mma16816(float* c, const uint32_t* a,
                                         uint32_t b0, uint32_t b1) {
    asm volatile(
        "mma.sync.aligned.m16n8k16.row.col.f32.bf16.bf16.f32 "
        "{%0,%1,%2,%3}, {%4,%5,%6,%7}, {%8,%9}, {%0,%1,%2,%3};"
        : "+f"(c[0]), "+f"(c[1]), "+f"(c[2]), "+f"(c[3])
        : "r"(a[0]), "r"(a[1]), "r"(a[2]), "r"(a[3]), "r"(b0), "r"(b1));
}

__device__ __forceinline__ void gemm_core(const char* sm, int offA_hi, int offA_lo,
                                          int offW_hi, int offW_lo,
                                          const float* sBias, __half* C,
                                          int rowBase, int M, int tid) {
    const int lane = tid & 31, wid = tid >> 5;
    const int gid = lane >> 2, tig = lane & 3;
    const int wr = wid & 3;
    const int wc = wid >> 2;

    float acc[2][8][4];
#pragma unroll
    for (int m = 0; m < 2; m++)
#pragma unroll
        for (int nt = 0; nt < 8; nt++)
#pragma unroll
            for (int j = 0; j < 4; j++) acc[m][nt][j] = 0.f;

    const uint32_t* Ahi = (const uint32_t*)(sm + offA_hi);
    const uint32_t* Alo = (const uint32_t*)(sm + offA_lo);
    const uint32_t* Whi = (const uint32_t*)(sm + offW_hi);
    const uint32_t* Wlo = (const uint32_t*)(sm + offW_lo);

#pragma unroll
    for (int p = 0; p < 3; p++) {
        const uint32_t* Aw = (p == 2) ? Alo : Ahi;
        const uint32_t* Bw = (p == 1) ? Wlo : Whi;
#pragma unroll
        for (int kc = 0; kc < 8; kc++) {
            int kw = kc * 8 + tig;
            uint32_t a[2][4];
#pragma unroll
            for (int m = 0; m < 2; m++) {
                int rb = wr * 32 + m * 16 + gid;
                a[m][0] = Aw[rb * PADW + kw];
                a[m][1] = Aw[(rb + 8) * PADW + kw];
                a[m][2] = Aw[rb * PADW + kw + 4];
                a[m][3] = Aw[(rb + 8) * PADW + kw + 4];
            }
#pragma unroll
            for (int nt = 0; nt < 8; nt++) {
                int nr = wc * 64 + nt * 8 + gid;
                uint32_t b0 = Bw[nr * PADW + kw];
                uint32_t b1 = Bw[nr * PADW + kw + 4];
                mma16816(acc[0][nt], a[0], b0, b1);
                mma16816(acc[1][nt], a[1], b0, b1);
            }
        }
    }
#pragma unroll
    for (int m = 0; m < 2; m++) {
        int row0 = rowBase + wr * 32 + m * 16 + gid;
#pragma unroll
        for (int nt = 0; nt < 8; nt++) {
            int col = wc * 64 + nt * 8 + 2 * tig;
            float bb0 = sBias[col], bb1 = sBias[col + 1];
            if (row0 < M) {
                __half2 o = make_half2(__float2half_rn(acc[m][nt][0] + bb0),
                                       __float2half_rn(acc[m][nt][1] + bb1));
                ((__half2*)C)[(size_t)row0 * 64 + (col >> 1)] = o;
            }
            if (row0 + 8 < M) {
                __half2 o = make_half2(__float2half_rn(acc[m][nt][2] + bb0),
                                       __float2half_rn(acc[m][nt][3] + bb1));
                ((__half2*)C)[(size_t)(row0 + 8) * 64 + (col >> 1)] = o;
            }
        }
    }
}

// ---- single-output GEMM (layer 1) ----
#define S_BIAS 0
#define S_AHI  512
#define S_ALO  (S_AHI + T_BYTES)
#define S_WHI  (S_ALO + T_BYTES)
#define S_WLO  (S_WHI + T_BYTES)
#define SMEM_MMA  (S_WLO + T_BYTES)            // 139776

__global__ __launch_bounds__(256, 1)
void k_gemm_mma(const float* __restrict__ A, const uint4* __restrict__ WhiG,
                const uint4* __restrict__ WloG, const float* __restrict__ bp,
                __half* __restrict__ C, int M) {
    extern __shared__ char sm2[];
    const int tid = threadIdx.x;
    const int rowBase = blockIdx.x * 128;
    if (tid < 128) ((float*)(sm2 + S_BIAS))[tid] = bp[tid];
#pragma unroll
    for (int i = 0; i < 8; i++) {
        int idx = tid + i * 256;
        int r = idx >> 4, q = idx & 15;
        ((uint4*)(sm2 + S_WHI))[r * 17 + q] = WhiG[idx];
        ((uint4*)(sm2 + S_WLO))[r * 17 + q] = WloG[idx];
    }
#pragma unroll
    for (int i = 0; i < 8; i++) {
        int idx = tid + i * 256;
        int r = idx >> 4, q = idx & 15;
        int grow = rowBase + r;
        float x[8] = {0.f, 0.f, 0.f, 0.f, 0.f, 0.f, 0.f, 0.f};
        if (grow < M) {
            float4 v0 = ((const float4*)A)[(size_t)grow * 32 + q * 2];
            float4 v1 = ((const float4*)A)[(size_t)grow * 32 + q * 2 + 1];
            x[0] = v0.x; x[1] = v0.y; x[2] = v0.z; x[3] = v0.w;
            x[4] = v1.x; x[5] = v1.y; x[6] = v1.z; x[7] = v1.w;
        }
        uint4 hv, lv;
        split8(x, hv, lv);
        ((uint4*)(sm2 + S_AHI))[r * 17 + q] = hv;
        ((uint4*)(sm2 + S_ALO))[r * 17 + q] = lv;
    }
    __syncthreads();
    gemm_core(sm2, S_AHI, S_ALO, S_WHI, S_WLO, (const float*)(sm2 + S_BIAS),
              C, rowBase, M, tid);
}

// ---- dual-output GEMM (layer 0: same A, two weight sets) ----
#define D_BIAS 0
#define D_AHI  1024
#define D_ALO  (D_AHI + T_BYTES)
#define D_W1HI (D_ALO + T_BYTES)
#define D_W1LO (D_W1HI + T_BYTES)
#define D_W2HI (D_W1LO + T_BYTES)
#define D_W2LO (D_W2HI + T_BYTES)
#define SMEM_MMA2 (D_W2LO + T_BYTES)           // 209920

__global__ __launch_bounds__(256, 1)
void k_gemm_mma2(const float* __restrict__ A,
                 const uint4* __restrict__ W1hiG, const uint4* __restrict__ W1loG,
                 const float* __restrict__ bp1, __half* __restrict__ C1,
                 const uint4* __restrict__ W2hiG, const uint4* __restrict__ W2loG,
                 const float* __restrict__ bp2, __half* __restrict__ C2, int M) {
    extern __shared__ char sm3[];
    const int tid = threadIdx.x;
    const int rowBase = blockIdx.x * 128;
    if (tid < 128) {
        ((float*)(sm3 + D_BIAS))[tid] = bp1[tid];
        ((float*)(sm3 + D_BIAS + 512))[tid] = bp2[tid];
    }
#pragma unroll
    for (int i = 0; i < 8; i++) {
        int idx = tid + i * 256;
        int r = idx >> 4, q = idx & 15;
        ((uint4*)(sm3 + D_W1HI))[r * 17 + q] = W1hiG[idx];
        ((uint4*)(sm3 + D_W1LO))[r * 17 + q] = W1loG[idx];
        ((uint4*)(sm3 + D_W2HI))[r * 17 + q] = W2hiG[idx];
        ((uint4*)(sm3 + D_W2LO))[r * 17 + q] = W2loG[idx];
    }
#pragma unroll
    for (int i = 0; i < 8; i++) {
        int idx = tid + i * 256;
        int r = idx >> 4, q = idx & 15;
        int grow = rowBase + r;
        float x[8] = {0.f, 0.f, 0.f, 0.f, 0.f, 0.f, 0.f, 0.f};
        if (grow < M) {
            float4 v0 = ((const float4*)A)[(size_t)grow * 32 + q * 2];
            float4 v1 = ((const float4*)A)[(size_t)grow * 32 + q * 2 + 1];
            x[0] = v0.x; x[1] = v0.y; x[2] = v0.z; x[3] = v0.w;
            x[4] = v1.x; x[5] = v1.y; x[6] = v1.z; x[7] = v1.w;
        }
        uint4 hv, lv;
        split8(x, hv, lv);
        ((uint4*)(sm3 + D_AHI))[r * 17 + q] = hv;
        ((uint4*)(sm3 + D_ALO))[r * 17 + q] = lv;
    }
    __syncthreads();
    gemm_core(sm3, D_AHI, D_ALO, D_W1HI, D_W1LO, (const float*)(sm3 + D_BIAS),
              C1, rowBase, M, tid);
    gemm_core(sm3, D_AHI, D_ALO, D_W2HI, D_W2LO, (const float*)(sm3 + D_BIAS + 512),
              C2, rowBase, M, tid);
}

// -------- column stats only (no write) --------
__global__ void k_stats(const float* __restrict__ src,
                        float* __restrict__ sum, float* __restrict__ sq, int n) {
    __shared__ float ssum[D], ssq[D];
    int tid = threadIdx.x;
    if (tid < D) { ssum[tid] = 0.f; ssq[tid] = 0.f; }
    __syncthreads();
    int lane = tid & 31;
    int warp = (blockIdx.x * blockDim.x + tid) >> 5;
    int nwarps = (gridDim.x * blockDim.x) >> 5;
    float4 ls = make_float4(0.f, 0.f, 0.f, 0.f);
    float4 lq = make_float4(0.f, 0.f, 0.f, 0.f);
    for (int row = warp; row < n; row += nwarps) {
        float4 v = ((const float4*)src)[(size_t)row * 32 + lane];
        ls.x += v.x; ls.y += v.y; ls.z += v.z; ls.w += v.w;
        lq.x += v.x * v.x; lq.y += v.y * v.y; lq.z += v.z * v.z; lq.w += v.w * v.w;
    }
    atomicAdd(&ssum[lane * 4 + 0], ls.x); atomicAdd(&ssum[lane * 4 + 1], ls.y);
    atomicAdd(&ssum[lane * 4 + 2], ls.z); atomicAdd(&ssum[lane * 4 + 3], ls.w);
    atomicAdd(&ssq [lane * 4 + 0], lq.x); atomicAdd(&ssq [lane * 4 + 1], lq.y);
    atomicAdd(&ssq [lane * 4 + 2], lq.z); atomicAdd(&ssq [lane * 4 + 3], lq.w);
    __syncthreads();
    if (tid < D) { atomicAdd(&sum[tid], ssum[tid]); atomicAdd(&sq[tid], ssq[tid]); }
}

// -------- row-normalize: dst = scale[row] * src/||src||  (scale nullptr -> 1) ----
__global__ void k_rownorm(const float* __restrict__ src, int M, float* __restrict__ dst,
                          int ldDst, float* __restrict__ dst2, int ldDst2,
                          const float* __restrict__ scale) {
    int w = (blockIdx.x * blockDim.x + threadIdx.x) >> 5;
    int lane = threadIdx.x & 31;
    if (w >= M) return;
    float4 v = ((const float4*)src)[(size_t)w * 32 + lane];
    float s = v.x * v.x + v.y * v.y + v.z * v.z + v.w * v.w;
#pragma unroll
    for (int o = 16; o; o >>= 1) s += __shfl_xor_sync(0xffffffffu, s, o);
    float sc = scale ? scale[w] : 1.f;
    float inv = sc / fmaxf(sqrtf(s), 1e-12f);
    float4 o4 = make_float4(v.x * inv, v.y * inv, v.z * inv, v.w * inv);
    ((float4*)(dst + (size_t)w * ldDst))[lane] = o4;
    if (dst2) ((float4*)(dst2 + (size_t)w * ldDst2))[lane] = o4;
}

// -------- CSR gather conv v2 (proven fastest): half-warp per edge, LDG.128,
//          4 edges per step, grid-stride node assignment --------
__device__ __forceinline__ void fma8(float* acc, uint4 g, uint4 x) {
    __half2* gh = (__half2*)&g;
    __half2* xh = (__half2*)&x;
#pragma unroll
    for (int i = 0; i < 4; i++) {
        float2 gf = __half22float2(gh[i]);
        float2 xf = __half22float2(xh[i]);
        acc[2 * i]     = fmaf(gf.x, xf.x, acc[2 * i]);
        acc[2 * i + 1] = fmaf(gf.y, xf.y, acc[2 * i + 1]);
    }
}

__global__ void k_gather(const __half* __restrict__ X, const __half* __restrict__ G,
                         const int* __restrict__ off, const int2* __restrict__ eSA,
                         float* __restrict__ rawH,
                         float* __restrict__ normDst, int ldNorm,
                         const float* __restrict__ ksc,
                         float* __restrict__ le, const float* __restrict__ lesc,
                         float* __restrict__ sum, float* __restrict__ sq, int n) {
    __shared__ float ssum[D], ssq[D];
    int tid = threadIdx.x;
    const bool doStats = (sum != nullptr);
    if (doStats) {
        if (tid < D) { ssum[tid] = 0.f; ssq[tid] = 0.f; }
        __syncthreads();
    }
    int lane = tid & 31;
    int sub = lane & 15, half = lane >> 4;
    int warp = (blockIdx.x * blockDim.x + tid) >> 5;
    int nwarps = (gridDim.x * blockDim.x) >> 5;
    const uint4* G4 = (const uint4*)G;
    const uint4* X4 = (const uint4*)X;
    float ls0 = 0.f, ls1 = 0.f, ls2 = 0.f, ls3 = 0.f;
    float lq0 = 0.f, lq1 = 0.f, lq2 = 0.f, lq3 = 0.f;

    for (int v = warp; v < n; v += nwarps) {
        int b0 = off[v], b1 = off[v + 1];
        float acc[8] = {0.f, 0.f, 0.f, 0.f, 0.f, 0.f, 0.f, 0.f};
        for (int base = b0; base < b1; base += 32) {
            int cnt = min(32, b1 - base);
            int2 sa = make_int2(0, 0);
            if (lane < cnt) sa = eSA[base + lane];
            int j = 0;
            for (; j + 4 <= cnt; j += 4) {
                int e0 = j + half, e1 = j + 2 + half;
                int s0 = __shfl_sync(0xffffffffu, sa.x, e0);
                int a0 = __shfl_sync(0xffffffffu, sa.y, e0);
                int s1 = __shfl_sync(0xffffffffu, sa.x, e1);
                int a1 = __shfl_sync(0xffffffffu, sa.y, e1);
                uint4 g0 = G4[a0 * 16 + sub];
                uint4 x0 = X4[(size_t)s0 * 16 + sub];
                uint4 g1 = G4[a1 * 16 + sub];
                uint4 x1 = X4[(size_t)s1 * 16 + sub];
                fma8(acc, g0, x0);
                fma8(acc, g1, x1);
            }
            for (; j < cnt; j += 2) {
                int e = min(j + half, cnt - 1);
                int s0 = __shfl_sync(0xffffffffu, sa.x, e);
                int a0 = __shfl_sync(0xffffffffu, sa.y, e);
                if (j + half < cnt) {
                    uint4 g = G4[a0 * 16 + sub];
                    uint4 x = X4[(size_t)s0 * 16 + sub];
                    fma8(acc, g, x);
                }
            }
        }
        // merge the two edge-halves (duplicate full row in both halves)
#pragma unroll
        for (int k = 0; k < 8; k++)
            acc[k] += __shfl_xor_sync(0xffffffffu, acc[k], 16);
        // row norm: reduce within the 16-lane half (covers all 128 cols)
        float ns = 0.f;
#pragma unroll
        for (int k = 0; k < 8; k++) ns += acc[k] * acc[k];
#pragma unroll
        for (int o = 1; o <= 8; o <<= 1) ns += __shfl_xor_sync(0xffffffffu, ns, o);
        float invB = 1.f / fmaxf(sqrtf(ns), 1e-12f);
        // this lane writes one float4: cols sub*8 + half*4 + [0,4)
        float4 w = make_float4(acc[half * 4 + 0], acc[half * 4 + 1],
                               acc[half * 4 + 2], acc[half * 4 + 3]);
        int q = sub * 2 + half;
        if (rawH) ((float4*)rawH)[(size_t)v * 32 + q] = w;
        float s1v = invB * ksc[v];
        ((float4*)(normDst + (size_t)v * ldNorm))[q] =
            make_float4(w.x * s1v, w.y * s1v, w.z * s1v, w.w * s1v);
        if (le) {
            float s2 = invB * lesc[v];
            ((float4*)(le + (size_t)v * 256))[q] =
                make_float4(w.x * s2, w.y * s2, w.z * s2, w.w * s2);
        }
        if (doStats) {
            ls0 += w.x; ls1 += w.y; ls2 += w.z; ls3 += w.w;
            lq0 += w.x * w.x; lq1 += w.y * w.y; lq2 += w.z * w.z; lq3 += w.w * w.w;
        }
    }
    if (doStats) {
        int cb = sub * 8 + half * 4;
        atomicAdd(&ssum[cb + 0], ls0); atomicAdd(&ssum[cb + 1], ls1);
        atomicAdd(&ssum[cb + 2], ls2); atomicAdd(&ssum[cb + 3], ls3);
        atomicAdd(&ssq [cb + 0], lq0); atomicAdd(&ssq [cb + 1], lq1);
        atomicAdd(&ssq [cb + 2], lq2); atomicAdd(&ssq [cb + 3], lq3);
        __syncthreads();
        if (tid < D) { atomicAdd(&sum[tid], ssum[tid]); atomicAdd(&sq[tid], ssq[tid]); }
    }
}

__global__ void k_rel_renorm(float* __restrict__ rf, int M) {
    int w = (blockIdx.x * blockDim.x + threadIdx.x) >> 5;
    int lane = threadIdx.x & 31;
    if (w >= M) return;
    float* rowp = rf + (size_t)w * 384;
    float4 v[3];
    float tot = 0.f;
#pragma unroll
    for (int j = 0; j < 3; j++) {
        v[j] = ((float4*)rowp)[j * 32 + lane];
        tot += v[j].x * v[j].x + v[j].y * v[j].y + v[j].z * v[j].z + v[j].w * v[j].w;
    }
#pragma unroll
    for (int o = 16; o; o >>= 1) tot += __shfl_xor_sync(0xffffffffu, tot, o);
    float it = 1.f / fmaxf(sqrtf(tot), 1e-12f);
#pragma unroll
    for (int j = 0; j < 3; j++)
        ((float4*)rowp)[j * 32 + lane] =
            make_float4(v[j].x * it, v[j].y * it, v[j].z * it, v[j].w * it);
}

// =============================== host orchestration ===============================
// Streams/events created ONCE per process (first call = correctness run, before
// the pre-capture memory baseline) and reused — teardown returns to baseline.
static cudaStream_t s_sB = 0, s_sC = 0, s_sD = 0;
static cudaEvent_t s_ev[12] = {0};

extern "C" void kernel_launch(void* const* d_in, const int* in_sizes, int n_in,
                              void* d_out, int out_size) {
    const float* ent      = (const float*)d_in[0];
    const float* rel      = (const float*)d_in[1];
    const float* W_inv    = (const float*)d_in[2];
    const float* b_inv    = (const float*)d_in[3];
    const float* bn_gamma = (const float*)d_in[4];
    const float* bn_beta  = (const float*)d_in[5];
    const float* rel_W    = (const float*)d_in[6];
    const float* rel_b    = (const float*)d_in[7];
    const float* ent_W    = (const float*)d_in[8];
    const float* ent_b    = (const float*)d_in[9];
    const float* s_W      = (const float*)d_in[10];
    const float* s_b      = (const float*)d_in[11];
    const float* conv_Wg  = (const float*)d_in[12];
    const float* conv_bg  = (const float*)d_in[13];
    const float* sconv_Wg = (const float*)d_in[14];
    const float* sconv_bg = (const float*)d_in[15];
    const int*   ei       = (const int*)d_in[16];
    const int*   cei      = (const int*)d_in[17];
    const int*   attr     = (const int*)d_in[18];

    const int n = in_sizes[0] / D;        // 100000
    const int E = in_sizes[18];           // 800000
    const float invN = 1.f / (float)n;

    float* out = (float*)d_out;
    float* FE = out;                                   // [n, 640]
    float* RF = out + (size_t)n * 640;                 // [2000, 384]
    float* LE = RF + (size_t)RELN * 384;               // [n, 256]
    float* LR = LE + (size_t)n * 256;                  // [2000, 128]

    float *HA, *HB, *rA, *rB, *bp1, *bp2, *st, *ksc, *lesc;
    __half *Xh1, *Xh2, *G1, *G2, *G1b, *G2b;
    unsigned *W1hi, *W1lo, *W2hi, *W2lo;
    int *cnt1, *cnt2, *cur1, *cur2, *off1, *off2, *bs1, *bs2;
    int2 *eSA1, *eSA2;
    cudaGetSymbolAddress((void**)&Xh1, g_Xh1);
    cudaGetSymbolAddress((void**)&Xh2, g_Xh2);
    cudaGetSymbolAddress((void**)&HA,  g_HA);
    cudaGetSymbolAddress((void**)&HB,  g_HB);
    cudaGetSymbolAddress((void**)&rA,  g_relA);
    cudaGetSymbolAddress((void**)&rB,  g_relB);
    cudaGetSymbolAddress((void**)&G1,  g_G1);
    cudaGetSymbolAddress((void**)&G2,  g_G2);
    cudaGetSymbolAddress((void**)&G1b, g_G1b);
    cudaGetSymbolAddress((void**)&G2b, g_G2b);
    cudaGetSymbolAddress((void**)&W1hi, g_W1hi);
    cudaGetSymbolAddress((void**)&W1lo, g_W1lo);
    cudaGetSymbolAddress((void**)&W2hi, g_W2hi);
    cudaGetSymbolAddress((void**)&W2lo, g_W2lo);
    cudaGetSymbolAddress((void**)&bp1, g_bp1);
    cudaGetSymbolAddress((void**)&bp2, g_bp2);
    cudaGetSymbolAddress((void**)&st,  g_stats);
    cudaGetSymbolAddress((void**)&ksc, g_ksc);
    cudaGetSymbolAddress((void**)&lesc,g_lesc);
    cudaGetSymbolAddress((void**)&cnt1,g_cnt1);
    cudaGetSymbolAddress((void**)&cnt2,g_cnt2);
    cudaGetSymbolAddress((void**)&cur1,g_cur1);
    cudaGetSymbolAddress((void**)&cur2,g_cur2);
    cudaGetSymbolAddress((void**)&off1,g_off1);
    cudaGetSymbolAddress((void**)&off2,g_off2);
    cudaGetSymbolAddress((void**)&bs1, g_bs1);
    cudaGetSymbolAddress((void**)&bs2, g_bs2);
    cudaGetSymbolAddress((void**)&eSA1,g_eSA1);
    cudaGetSymbolAddress((void**)&eSA2,g_eSA2);

    float* stE  = st;
    float* stHA = st + 2 * D;
    float* stHB = st + 4 * D;

    cudaFuncSetAttribute(k_gemm_mma,  cudaFuncAttributeMaxDynamicSharedMemorySize, SMEM_MMA);
    cudaFuncSetAttribute(k_gemm_mma2, cudaFuncAttributeMaxDynamicSharedMemorySize, SMEM_MMA2);

    const int gemmGrid   = (n + 127) / 128;
    const int gathGrid   = 1024;
    const int edgeGrid   = (E + 255) / 256;
    const int nbScan     = (n + CHUNK - 1) / CHUNK;
    const int rnBigGrid  = (n * 32 + 255) / 256;
    const int rnRelGrid  = (RELN * 32 + 255) / 256;

    // ---- streams + events: create once, first call only (pre-capture) ----
    if (s_sB == 0) {
        cudaStreamCreateWithFlags(&s_sB, cudaStreamNonBlocking);
        cudaStreamCreateWithFlags(&s_sC, cudaStreamNonBlocking);
        cudaStreamCreateWithFlags(&s_sD, cudaStreamNonBlocking);
        for (int i = 0; i < 12; i++)
            cudaEventCreateWithFlags(&s_ev[i], cudaEventDisableTiming);
    }
    cudaStream_t sB = s_sB, sC = s_sC, sD = s_sD;
    cudaEvent_t eFork = s_ev[0], eH2 = s_ev[1], eScales = s_ev[2], eX = s_ev[3],
                eGate = s_ev[4], eRel = s_ev[5], eG1 = s_ev[6], eG2 = s_ev[7],
                eF2 = s_ev[8], eDend = s_ev[9], eCend = s_ev[10];

    // ---- fork ----
    cudaEventRecord(eFork, 0);
    cudaStreamWaitEvent(sB, eFork, 0);
    cudaStreamWaitEvent(sC, eFork, 0);
    cudaStreamWaitEvent(sD, eFork, 0);

    // ---- stream D: relation/gate chain (no deps, starts at t=0) ----
    cudaMemcpyAsync(rA, rel, (size_t)1000 * D * sizeof(float),
                    cudaMemcpyDeviceToDevice, sD);
    k_small_gemm<<<125, 128, 0, sD>>>(rel, W_inv, b_inv, rA + 1000 * D, 1000);
    k_rownorm<<<rnRelGrid, 256, 0, sD>>>(rA, RELN, RF, 384, nullptr, 0, nullptr);
    k_small_gemm<<<250, 128, 0, sD>>>(rA, rel_W, rel_b, rB, RELN);
    k_rownorm<<<rnRelGrid, 256, 0, sD>>>(rB, RELN, RF + 128, 384, nullptr, 0, nullptr);
    k_gate_gemm2<<<250, 128, 0, sD>>>(rB, conv_Wg, conv_bg, G1,
                                      sconv_Wg, sconv_bg, G2, RELN);
    cudaEventRecord(eGate, sD);
    k_small_gemm<<<250, 128, 0, sD>>>(rB, rel_W + D * D, rel_b + D, rA, RELN);
    k_rownorm<<<rnRelGrid, 256, 0, sD>>>(rA, RELN, RF + 256, 384, LR, 128, nullptr);
    k_gate_gemm2<<<250, 128, 0, sD>>>(rA, conv_Wg + D * D, conv_bg + D, G1b,
                                      sconv_Wg + D * D, sconv_bg + D, G2b, RELN);
    cudaEventRecord(eRel, sD);
    k_rel_renorm<<<rnRelGrid, 256, 0, sD>>>(RF, RELN);
    cudaEventRecord(eDend, sD);

    // ---- stream C: ent stats -> preps -> dual GEMM (no CSR dep) ----
    cudaMemsetAsync(st, 0, 6 * D * sizeof(float), sC);
    k_stats<<<512, 256, 0, sC>>>(ent, stE, stE + D, n);
    k_prep_wb<<<1, 128, 0, sC>>>(stE, stE + D, bn_gamma, bn_beta, ent_W, ent_b,
                                 W1hi, W1lo, bp1, invN);
    k_prep_wb<<<1, 128, 0, sC>>>(stE, stE + D, bn_gamma, bn_beta, s_W, s_b,
                                 W2hi, W2lo, bp2, invN);
    k_gemm_mma2<<<gemmGrid, 256, SMEM_MMA2, sC>>>(ent,
        (const uint4*)W1hi, (const uint4*)W1lo, bp1, Xh1,
        (const uint4*)W2hi, (const uint4*)W2lo, bp2, Xh2, n);
    cudaEventRecord(eX, sC);

    // ---- stream B: CSR graph2 ----
    cudaMemsetAsync(cnt2, 0, n * sizeof(int), sB);
    k_hist<<<edgeGrid, 256, 0, sB>>>(cei + E, cnt2, E);
    cudaEventRecord(eH2, sB);
    k_scan_sum<<<nbScan, CHUNK, 0, sB>>>(cnt2, bs2, n);
    k_scan_top<<<1, 256, 0, sB>>>(bs2, nbScan);
    k_scan_out<<<nbScan, CHUNK, 0, sB>>>(cnt2, bs2, off2, cur2, n, E);
    k_fill<<<edgeGrid, 256, 0, sB>>>(cei, cei + E, attr, cur2, eSA2, E);

    // ---- stream A (=0): CSR graph1 (scales right after hists) ----
    cudaMemsetAsync(cnt1, 0, n * sizeof(int), 0);
    k_hist<<<edgeGrid, 256, 0, 0>>>(ei + E, cnt1, E);
    cudaStreamWaitEvent(0, eH2, 0);
    k_scales<<<(n + 255) / 256, 256, 0, 0>>>(cnt1, cnt2, ksc, lesc, n);
    cudaEventRecord(eScales, 0);
    k_scan_sum<<<nbScan, CHUNK, 0, 0>>>(cnt1, bs1, n);
    k_scan_top<<<1, 256, 0, 0>>>(bs1, nbScan);
    k_scan_out<<<nbScan, CHUNK, 0, 0>>>(cnt1, bs1, off1, cur1, n, E);
    k_fill<<<edgeGrid, 256, 0, 0>>>(ei, ei + E, attr, cur1, eSA1, E);

    // block0 = ksc * normalize(ent) on C, overlapped with gathers
    cudaStreamWaitEvent(sC, eScales, 0);
    k_rownorm<<<rnBigGrid, 256, 0, sC>>>(ent, n, FE, 640, nullptr, 0, ksc);
    cudaEventRecord(eCend, sC);

    // ---- layer-0 gathers (A and B, concurrent) ----
    cudaStreamWaitEvent(0, eX, 0);
    cudaStreamWaitEvent(0, eGate, 0);
    k_gather<<<gathGrid, 256, 0, 0>>>(Xh1, G1, off1, eSA1, HA, FE + 256, 640, ksc,
                                      nullptr, nullptr, stHA, stHA + D, n);
    cudaEventRecord(eG1, 0);
    cudaStreamWaitEvent(sB, eX, 0);
    cudaStreamWaitEvent(sB, eGate, 0);
    cudaStreamWaitEvent(sB, eScales, 0);
    k_gather<<<gathGrid, 256, 0, sB>>>(Xh2, G2, off2, eSA2, HB, FE + 128, 640, ksc,
                                       nullptr, nullptr, stHB, stHB + D, n);
    cudaEventRecord(eG2, sB);

    // ---- layer-1 branch on A: HB path (needs gather2 done) ----
    cudaStreamWaitEvent(0, eG2, 0);
    k_prep_wb<<<1, 128, 0, 0>>>(stHB, stHB + D, bn_gamma + D, bn_beta + D,
                                ent_W + D * D, ent_b + D, W1hi, W1lo, bp1, invN);
    k_gemm_mma<<<gemmGrid, 256, SMEM_MMA, 0>>>(HB, (const uint4*)W1hi,
                                               (const uint4*)W1lo, bp1, Xh1, n);
    cudaStreamWaitEvent(0, eRel, 0);
    k_gather<<<gathGrid, 256, 0, 0>>>(Xh1, G1b, off1, eSA1, nullptr, FE + 512, 640,
                                      ksc, LE + 128, lesc, nullptr, nullptr, n);

    // ---- layer-1 branch on B: HA path (needs gather1 done) ----
    cudaStreamWaitEvent(sB, eG1, 0);
    k_prep_wb<<<1, 128, 0, sB>>>(stHA, stHA + D, bn_gamma + D, bn_beta + D,
                                 s_W + D * D, s_b + D, W2hi, W2lo, bp2, invN);
    k_gemm_mma<<<gemmGrid, 256, SMEM_MMA, sB>>>(HA, (const uint4*)W2hi,
                                                (const uint4*)W2lo, bp2, Xh2, n);
    cudaStreamWaitEvent(sB, eRel, 0);
    k_gather<<<gathGrid, 256, 0, sB>>>(Xh2, G2b, off2, eSA2, nullptr, FE + 384, 640,
                                       ksc, LE, lesc, nullptr, nullptr, n);
    cudaEventRecord(eF2, sB);

    // ---- join everything back onto the origin stream ----
    cudaStreamWaitEvent(0, eF2, 0);
    cudaStreamWaitEvent(0, eCend, 0);
    cudaStreamWaitEvent(0, eDend, 0);
}